// round 11
// baseline (speedup 1.0000x reference)
#include <cuda_runtime.h>
#include <cuda_fp16.h>
#include <cstdint>
#include <cstddef>

// Problem constants
#define DM      512
#define DFF     2048
#define NB      8
#define SEQ     1024
#define NHEAD   8
#define EHEAD   64
#define ROWS    (NB*SEQ)     // 8192
#define NLAYERS 4
#define LN_EPS  1e-5f

// ---------------- scratch (device globals; no allocations allowed) --------
__device__ __half g_qh [ROWS*DM];    // Q (pre-scaled 1/8)
__device__ __half g_kh [ROWS*DM];
__device__ __half g_vth[DM*ROWS];    // V^T [col][token]
__device__ __half g_oh [ROWS*DM];    // attention out
__device__ __half g_xh [ROWS*DM];    // fp16 copy of layer input
__device__ __half g_h1h[ROWS*DM];    // fp16 copy of post-LN1
__device__ __half g_ffh[ROWS*DFF];   // ReLU(FFN1) in fp16
__device__ float  g_h  [ROWS*DM];
__device__ float  g_h1 [ROWS*DM];
__device__ float  g_h2 [ROWS*DM];
__device__ float  g_x  [ROWS*DM];
// fp16 weights (converted once per launch)
__device__ __half g_wq[NLAYERS*DM*DM];
__device__ __half g_wk[NLAYERS*DM*DM];
__device__ __half g_wv[NLAYERS*DM*DM];
__device__ __half g_wo[NLAYERS*DM*DM];
__device__ __half g_w1[NLAYERS*DM*DFF];
__device__ __half g_w2[NLAYERS*DFF*DM];

// ---------------- helpers ---------------------------------------------------
__device__ __forceinline__ uint32_t f2h2(float a, float b) {
    __half2 h = __floats2half2_rn(a, b);
    return *(uint32_t*)&h;
}
__device__ __forceinline__ void ldsm4(uint32_t* r, uint32_t addr) {
    asm volatile("ldmatrix.sync.aligned.m8n8.x4.shared.b16 {%0,%1,%2,%3}, [%4];\n"
                 : "=r"(r[0]), "=r"(r[1]), "=r"(r[2]), "=r"(r[3]) : "r"(addr));
}
__device__ __forceinline__ void ldsm4t(uint32_t* r, uint32_t addr) {
    asm volatile("ldmatrix.sync.aligned.m8n8.x4.trans.shared.b16 {%0,%1,%2,%3}, [%4];\n"
                 : "=r"(r[0]), "=r"(r[1]), "=r"(r[2]), "=r"(r[3]) : "r"(addr));
}
__device__ __forceinline__ void mma_f16(float* d, const uint32_t* a,
                                        uint32_t b0, uint32_t b1) {
    asm volatile(
        "mma.sync.aligned.m16n8k16.row.col.f32.f16.f16.f32 "
        "{%0,%1,%2,%3},{%4,%5,%6,%7},{%8,%9},{%0,%1,%2,%3};\n"
        : "+f"(d[0]), "+f"(d[1]), "+f"(d[2]), "+f"(d[3])
        : "r"(a[0]), "r"(a[1]), "r"(a[2]), "r"(a[3]), "r"(b0), "r"(b1));
}
__device__ __forceinline__ uint32_t smem_u32(const void* p) {
    return (uint32_t)__cvta_generic_to_shared(p);
}
__device__ __forceinline__ void cpa16(uint32_t dst, const void* src) {
    asm volatile("cp.async.ca.shared.global [%0], [%1], 16;\n"
                 :: "r"(dst), "l"(src) : "memory");
}
__device__ __forceinline__ void cpa_commit() {
    asm volatile("cp.async.commit_group;\n" ::: "memory");
}
template<int N>
__device__ __forceinline__ void cpa_wait() {
    asm volatile("cp.async.wait_group %0;\n" :: "n"(N) : "memory");
}

// ---------------- fp32 -> fp16 bulk convert (all 7 arrays, one launch) -----
__global__ __launch_bounds__(256)
void f2h_all(const float4* s0, uint2* d0, int n0,
             const float4* s1, uint2* d1, int n1,
             const float4* s2, uint2* d2, int n2,
             const float4* s3, uint2* d3, int n3,
             const float4* s4, uint2* d4, int n4,
             const float4* s5, uint2* d5, int n5,
             const float4* s6, uint2* d6, int n6)
{
    const float4* s; uint2* d; int n;
    switch (blockIdx.y) {
        case 0: s = s0; d = d0; n = n0; break;
        case 1: s = s1; d = d1; n = n1; break;
        case 2: s = s2; d = d2; n = n2; break;
        case 3: s = s3; d = d3; n = n3; break;
        case 4: s = s4; d = d4; n = n4; break;
        case 5: s = s5; d = d5; n = n5; break;
        default: s = s6; d = d6; n = n6; break;
    }
    int i = blockIdx.x*blockDim.x + threadIdx.x;
    if (i < n) {
        float4 v = s[i];
        uint2 o;
        o.x = f2h2(v.x, v.y);
        o.y = f2h2(v.z, v.w);
        d[i] = o;
    }
}

// ---------------------------------------------------------------------------
// GEMM core: BM=256, BN=128, BK=32, 256 thr = 8 warps (4m x 2n),
// warp tile 64x64, m16n8k16, 4-stage cp.async ring in dynamic smem.
// Halves smem-read bytes per MMA vs the 32x64 warp tile.
// ---------------------------------------------------------------------------
#define GPA 40
#define GPB 136
#define ABUF (256*GPA)            // halfs per A stage (10240)
#define BBUF (32*GPB)             // halfs per B stage (4352)
#define GSTAGES 4
#define GSMEM_BYTES (GSTAGES*(ABUF+BBUF)*2)   // 116736 B

// issue one k-tile's cp.async into stage st
#define GEMM_ISSUE(Aptr, Bptr, Kdim, Ndim, st, k0)                              \
    {                                                                           \
        const uint32_t oA = (uint32_t)((st)*ABUF*2);                            \
        const uint32_t oB = (uint32_t)((st)*BBUF*2);                            \
        _Pragma("unroll")                                                       \
        for (int j = 0; j < 4; j++)                                             \
            cpa16(sAu + oA + dA0 + (uint32_t)(j*64*GPA*2),                      \
                  (Aptr) + (size_t)(ar0 + j*64)*(Kdim) + (k0) + ak0);           \
        cpa16(sBu + oB + dB0, (Bptr) + (size_t)((k0) + bk0)*(Ndim) + bn0);      \
        cpa16(sBu + oB + dB1, (Bptr) + (size_t)((k0) + bk1)*(Ndim) + bn0);      \
    }

#define GEMM_MAINLOOP(Aptr, Bptr, Kdim, Ndim)                                   \
    __half* smA = dsm;                                                          \
    __half* smB = dsm + GSTAGES*ABUF;                                           \
    const int ar0 = tid >> 2,  ak0 = (tid & 3) << 3;                            \
    const int bk0 = tid >> 4,  bn0 = (tid & 15) << 3;                           \
    const int bk1 = bk0 + 16;                                                   \
    const uint32_t sAu = smem_u32(smA);                                         \
    const uint32_t sBu = smem_u32(smB);                                         \
    const uint32_t dA0 = (uint32_t)((ar0*GPA + ak0) << 1);                      \
    const uint32_t dB0 = (uint32_t)((bk0*GPB + bn0) << 1);                      \
    const uint32_t dB1 = (uint32_t)((bk1*GPB + bn0) << 1);                      \
    uint32_t aAd[4], bAd[4];                                                    \
    _Pragma("unroll")                                                           \
    for (int mi = 0; mi < 4; mi++)                                              \
        aAd[mi] = sAu + (((wm*64 + mi*16 + (lane & 15))*GPA + (lane >> 4)*8) << 1); \
    _Pragma("unroll")                                                           \
    for (int nt = 0; nt < 4; nt++)                                              \
        bAd[nt] = sBu + ((((lane & 7) + ((lane >> 3) & 1)*8)*GPB                \
                          + wn*64 + nt*16 + (lane >> 4)*8) << 1);               \
    float acc[4][8][4];                                                         \
    _Pragma("unroll")                                                           \
    for (int mi = 0; mi < 4; mi++)                                              \
        _Pragma("unroll")                                                       \
        for (int ni = 0; ni < 8; ni++)                                          \
            _Pragma("unroll")                                                   \
            for (int c = 0; c < 4; c++) acc[mi][ni][c] = 0.f;                   \
    const int KT = (Kdim) >> 5;                                                 \
    GEMM_ISSUE(Aptr, Bptr, Kdim, Ndim, 0, 0)  cpa_commit();                     \
    GEMM_ISSUE(Aptr, Bptr, Kdim, Ndim, 1, 32) cpa_commit();                     \
    GEMM_ISSUE(Aptr, Bptr, Kdim, Ndim, 2, 64) cpa_commit();                     \
    for (int kt = 0; kt < KT; kt++) {                                           \
        const int st = kt & (GSTAGES - 1);                                      \
        cpa_wait<GSTAGES - 2>();                                                \
        __syncthreads();                                                        \
        if (kt + 3 < KT) {                                                      \
            const int ns = (kt + 3) & (GSTAGES - 1);                            \
            GEMM_ISSUE(Aptr, Bptr, Kdim, Ndim, ns, (kt + 3)*32)                 \
        }                                                                       \
        cpa_commit();                                                           \
        const uint32_t boA = (uint32_t)(st*ABUF*2);                             \
        const uint32_t boB = (uint32_t)(st*BBUF*2);                             \
        _Pragma("unroll")                                                       \
        for (int kh = 0; kh < 2; kh++) {                                        \
            uint32_t af[4][4], bf[4][4];                                        \
            _Pragma("unroll")                                                   \
            for (int mi = 0; mi < 4; mi++)                                      \
                ldsm4(af[mi], aAd[mi] + boA + kh*32);                           \
            _Pragma("unroll")                                                   \
            for (int nt = 0; nt < 4; nt++)                                      \
                ldsm4t(bf[nt], bAd[nt] + boB + kh*16*GPB*2);                    \
            _Pragma("unroll")                                                   \
            for (int nt = 0; nt < 4; nt++) {                                    \
                _Pragma("unroll")                                               \
                for (int mi = 0; mi < 4; mi++) {                                \
                    mma_f16(acc[mi][2*nt],   af[mi], bf[nt][0], bf[nt][1]);     \
                    mma_f16(acc[mi][2*nt+1], af[mi], bf[nt][2], bf[nt][3]);     \
                }                                                               \
            }                                                                   \
        }                                                                       \
    }

// ---------------------------------------------------------------------------
// General fp16 GEMM with fused epilogues.
//  EPI 1: half out, bias+relu   EPI 2: f32 out, bias+residual
// ---------------------------------------------------------------------------
template<int EPI>
__global__ __launch_bounds__(256, 1)
void gemm_h(const __half* __restrict__ A, const __half* __restrict__ B,
            const float* __restrict__ bias, const float* __restrict__ res,
            void* __restrict__ Cv, int M, int N, int K)
{
    extern __shared__ __half dsm[];

    const int tid = threadIdx.x;
    const int lane = tid & 31, wid = tid >> 5;
    const int wm = wid & 3, wn = wid >> 2;
    const int bx = blockIdx.x, by = blockIdx.y;

    const __half* Ag = A + (size_t)(by*256)*K;
    const __half* Bg = B + (size_t)bx*128;

    GEMM_MAINLOOP(Ag, Bg, K, N)

    const int r0 = (by*256) + wm*64 + (lane >> 2);
#pragma unroll
    for (int mi = 0; mi < 4; mi++) {
        const int gr = r0 + mi*16;
#pragma unroll
        for (int ni = 0; ni < 8; ni++) {
            const int gc = (bx*128) + wn*64 + (ni >> 1)*16 + (ni & 1)*8
                         + ((lane & 3) << 1);
            const float2 bia = *(const float2*)(bias + gc);
            float2 v0 = make_float2(acc[mi][ni][0] + bia.x, acc[mi][ni][1] + bia.y);
            float2 v1 = make_float2(acc[mi][ni][2] + bia.x, acc[mi][ni][3] + bia.y);
            if (EPI == 1) {
                v0.x = fmaxf(v0.x, 0.f); v0.y = fmaxf(v0.y, 0.f);
                v1.x = fmaxf(v1.x, 0.f); v1.y = fmaxf(v1.y, 0.f);
                __half* Ch = (__half*)Cv;
                *(__half2*)(Ch + (size_t)gr*N + gc)     = __floats2half2_rn(v0.x, v0.y);
                *(__half2*)(Ch + (size_t)(gr+8)*N + gc) = __floats2half2_rn(v1.x, v1.y);
            } else {  // EPI == 2
                const float2 r_0 = *(const float2*)(res + (size_t)gr*N + gc);
                const float2 r_1 = *(const float2*)(res + (size_t)(gr+8)*N + gc);
                v0.x += r_0.x; v0.y += r_0.y;
                v1.x += r_1.x; v1.y += r_1.y;
                float* Cf = (float*)Cv;
                *(float2*)(Cf + (size_t)gr*N + gc)     = v0;
                *(float2*)(Cf + (size_t)(gr+8)*N + gc) = v1;
            }
        }
    }
}

// ---------------------------------------------------------------------------
// Fused QKV projection: grid (12, 32). bx>>2 selects Q/K/V.
// ---------------------------------------------------------------------------
__global__ __launch_bounds__(256, 1)
void gemm_qkv(const __half* __restrict__ A,
              const __half* __restrict__ Bq, const __half* __restrict__ Bk,
              const __half* __restrict__ Bv,
              const float* __restrict__ bq, const float* __restrict__ bk,
              const float* __restrict__ bv,
              __half* __restrict__ Oq, __half* __restrict__ Ok,
              __half* __restrict__ Ovt)
{
    extern __shared__ __half dsm[];

    const int tid = threadIdx.x;
    const int lane = tid & 31, wid = tid >> 5;
    const int wm = wid & 3, wn = wid >> 2;
    const int sel = blockIdx.x >> 2, bx = blockIdx.x & 3;
    const int by = blockIdx.y;
    const int N = DM, K = DM;

    const __half* B  = (sel == 0) ? Bq : (sel == 1) ? Bk : Bv;
    const float* bia_p = (sel == 0) ? bq : (sel == 1) ? bk : bv;

    const __half* Ag = A + (size_t)(by*256)*K;
    const __half* Bg = B + (size_t)bx*128;

    GEMM_MAINLOOP(Ag, Bg, K, N)

    const int r0 = (by*256) + wm*64 + (lane >> 2);
#pragma unroll
    for (int mi = 0; mi < 4; mi++) {
        const int gr = r0 + mi*16;
#pragma unroll
        for (int ni = 0; ni < 8; ni++) {
            const int gc = (bx*128) + wn*64 + (ni >> 1)*16 + (ni & 1)*8
                         + ((lane & 3) << 1);
            const float2 bia = *(const float2*)(bia_p + gc);
            float2 v0 = make_float2(acc[mi][ni][0] + bia.x, acc[mi][ni][1] + bia.y);
            float2 v1 = make_float2(acc[mi][ni][2] + bia.x, acc[mi][ni][3] + bia.y);
            if (sel == 0) {
                *(__half2*)(Oq + (size_t)gr*N + gc) =
                    __floats2half2_rn(v0.x*0.125f, v0.y*0.125f);
                *(__half2*)(Oq + (size_t)(gr+8)*N + gc) =
                    __floats2half2_rn(v1.x*0.125f, v1.y*0.125f);
            } else if (sel == 1) {
                *(__half2*)(Ok + (size_t)gr*N + gc)     = __floats2half2_rn(v0.x, v0.y);
                *(__half2*)(Ok + (size_t)(gr+8)*N + gc) = __floats2half2_rn(v1.x, v1.y);
            } else {
                Ovt[(size_t)gc*ROWS + gr]         = __float2half_rn(v0.x);
                Ovt[(size_t)(gc+1)*ROWS + gr]     = __float2half_rn(v0.y);
                Ovt[(size_t)gc*ROWS + gr + 8]     = __float2half_rn(v1.x);
                Ovt[(size_t)(gc+1)*ROWS + gr + 8] = __float2half_rn(v1.y);
            }
        }
    }
}

// ---------------------------------------------------------------------------
// FP16 flash attention, 64 q-rows / 128 threads / 4 warps per CTA,
// 2 CTAs per SM. K-tile 128 keys double-buffered; V from V^T. (unchanged)
// ---------------------------------------------------------------------------
#define AT_PA 136
#define AT_PK 72
#define AT_AH (64*AT_PA)
#define AT_KH (128*AT_PK)
#define AT_VH (64*AT_PA)
#define AT_OFF_K AT_AH
#define AT_OFF_V (AT_OFF_K + 2*AT_KH)
#define AT_SMEM_BYTES ((AT_OFF_V + 2*AT_VH)*2)   // 89088 B

__global__ __launch_bounds__(128, 2)
void attn_f16(const __half* __restrict__ Qh, const __half* __restrict__ Kh,
              const __half* __restrict__ Vth, __half* __restrict__ Oh)
{
    extern __shared__ __half smh[];
    __half* sA = smh;

    const int n = blockIdx.z, h = blockIdx.y;
    const int tid = threadIdx.x, lane = tid & 31, w = tid >> 5;
    const size_t base  = ((size_t)n*SEQ)*DM + h*EHEAD;
    const size_t vbase = ((size_t)h*EHEAD)*ROWS + (size_t)n*SEQ;
    const int q0 = blockIdx.x * 64;

    const uint32_t sAu = smem_u32(sA);
    const uint32_t sKu = smem_u32(smh + AT_OFF_K);
    const uint32_t sVu = smem_u32(smh + AT_OFF_V);

#pragma unroll
    for (int j = 0; j < 4; j++) {
        int idx = j*128 + tid;
        int r = idx >> 3, c8 = (idx & 7) << 3;
        cpa16(sAu + (uint32_t)((r*AT_PA + c8) << 1),
              Qh + base + (size_t)(q0 + r)*DM + c8);
    }
    cpa_commit();
#pragma unroll
    for (int j = 0; j < 8; j++) {
        int idx = j*128 + tid;
        int r = idx >> 3, c8 = (idx & 7) << 3;
        cpa16(sKu + (uint32_t)((r*AT_PK + c8) << 1),
              Kh + base + (size_t)r*DM + c8);
    }
#pragma unroll
    for (int j = 0; j < 8; j++) {
        int idx = j*128 + tid;
        int r = idx >> 4, c8 = (idx & 15) << 3;
        cpa16(sVu + (uint32_t)((r*AT_PA + c8) << 1),
              Vth + vbase + (size_t)r*ROWS + c8);
    }
    cpa_commit();

    cpa_wait<1>();
    __syncthreads();

    const uint32_t aBase = sAu + (((w*16 + (lane & 15))*AT_PA + (lane >> 4)*8) << 1);
    uint32_t aQ[4][4];
#pragma unroll
    for (int ks = 0; ks < 4; ks++) ldsm4(aQ[ks], aBase + ks*32);

    uint32_t bK[8], bV[4];
#pragma unroll
    for (int p = 0; p < 8; p++)
        bK[p] = sKu + (((p*16 + (lane & 7) + ((lane >> 3) & 1)*8)*AT_PK
                        + (lane >> 4)*8) << 1);
#pragma unroll
    for (int p = 0; p < 4; p++)
        bV[p] = sVu + (((p*16 + (lane & 7) + ((lane >> 3) & 1)*8)*AT_PA
                        + (lane >> 4)*8) << 1);

    float accO[8][4];
#pragma unroll
    for (int ni = 0; ni < 8; ni++)
#pragma unroll
        for (int c = 0; c < 4; c++) accO[ni][c] = 0.f;
    float m0 = -1e30f, m1 = -1e30f, l0 = 0.f, l1 = 0.f;

    const int rA = w*16 + (lane >> 2);
    __half* pr0 = &sA[rA*AT_PA + 2*(lane & 3)];
    __half* pr1 = pr0 + 8*AT_PA;

    for (int kt = 0; kt < SEQ/128; kt++) {
        const int buf = kt & 1;
        if (kt + 1 < SEQ/128) {
            const int nb = buf ^ 1;
            const uint32_t ko = (uint32_t)(nb * AT_KH) << 1;
            const uint32_t vo = (uint32_t)(nb * AT_VH) << 1;
#pragma unroll
            for (int j = 0; j < 8; j++) {
                int idx = j*128 + tid;
                int r = idx >> 3, c8 = (idx & 7) << 3;
                cpa16(sKu + ko + (uint32_t)((r*AT_PK + c8) << 1),
                      Kh + base + (size_t)((kt+1)*128 + r)*DM + c8);
            }
#pragma unroll
            for (int j = 0; j < 8; j++) {
                int idx = j*128 + tid;
                int r = idx >> 4, c8 = (idx & 15) << 3;
                cpa16(sVu + vo + (uint32_t)((r*AT_PA + c8) << 1),
                      Vth + vbase + (size_t)r*ROWS + (kt+1)*128 + c8);
            }
            cpa_commit();
            cpa_wait<1>();
        } else {
            cpa_wait<0>();
        }
        __syncthreads();

        const uint32_t ko = (uint32_t)(buf * AT_KH) << 1;
        const uint32_t vo = (uint32_t)(buf * AT_VH) << 1;

        float accS[16][4];
#pragma unroll
        for (int t = 0; t < 16; t++)
#pragma unroll
            for (int c = 0; c < 4; c++) accS[t][c] = 0.f;
#pragma unroll
        for (int ks = 0; ks < 4; ks++) {
#pragma unroll
            for (int p = 0; p < 8; p++) {
                uint32_t bf[4];
                ldsm4(bf, bK[p] + ko + ks*32);
                mma_f16(accS[2*p],   aQ[ks], bf[0], bf[2]);
                mma_f16(accS[2*p+1], aQ[ks], bf[1], bf[3]);
            }
        }

        float rmax0 = -1e30f, rmax1 = -1e30f;
#pragma unroll
        for (int t = 0; t < 16; t++) {
            rmax0 = fmaxf(rmax0, fmaxf(accS[t][0], accS[t][1]));
            rmax1 = fmaxf(rmax1, fmaxf(accS[t][2], accS[t][3]));
        }
        rmax0 = fmaxf(rmax0, __shfl_xor_sync(0xffffffffu, rmax0, 1));
        rmax0 = fmaxf(rmax0, __shfl_xor_sync(0xffffffffu, rmax0, 2));
        rmax1 = fmaxf(rmax1, __shfl_xor_sync(0xffffffffu, rmax1, 1));
        rmax1 = fmaxf(rmax1, __shfl_xor_sync(0xffffffffu, rmax1, 2));
        const float mn0 = fmaxf(m0, rmax0), mn1 = fmaxf(m1, rmax1);
        const float cr0 = __expf(m0 - mn0), cr1 = __expf(m1 - mn1);
        m0 = mn0; m1 = mn1;
        l0 *= cr0; l1 *= cr1;
#pragma unroll
        for (int ni = 0; ni < 8; ni++) {
            accO[ni][0] *= cr0; accO[ni][1] *= cr0;
            accO[ni][2] *= cr1; accO[ni][3] *= cr1;
        }
#pragma unroll
        for (int t = 0; t < 16; t++) {
            float p0 = __expf(accS[t][0] - m0), p1 = __expf(accS[t][1] - m0);
            float p2 = __expf(accS[t][2] - m1), p3 = __expf(accS[t][3] - m1);
            l0 += p0 + p1; l1 += p2 + p3;
            *(__half2*)(pr0 + t*8) = __floats2half2_rn(p0, p1);
            *(__half2*)(pr1 + t*8) = __floats2half2_rn(p2, p3);
        }
        __syncwarp();

#pragma unroll
        for (int ks = 0; ks < 8; ks++) {
            uint32_t aP[4];
            ldsm4(aP, aBase + ks*32);
#pragma unroll
            for (int p = 0; p < 4; p++) {
                uint32_t bf[4];
                ldsm4(bf, bV[p] + vo + ks*32);
                mma_f16(accO[2*p],   aP, bf[0], bf[2]);
                mma_f16(accO[2*p+1], aP, bf[1], bf[3]);
            }
        }
        __syncthreads();
    }

    l0 += __shfl_xor_sync(0xffffffffu, l0, 1);
    l0 += __shfl_xor_sync(0xffffffffu, l0, 2);
    l1 += __shfl_xor_sync(0xffffffffu, l1, 1);
    l1 += __shfl_xor_sync(0xffffffffu, l1, 2);
    const float inv0 = 1.f / l0, inv1 = 1.f / l1;
    const int gr0 = q0 + w*16 + (lane >> 2);
    const int cc = 2*(lane & 3);
#pragma unroll
    for (int ni = 0; ni < 8; ni++) {
        *(__half2*)(Oh + base + (size_t)gr0*DM + ni*8 + cc) =
            __floats2half2_rn(accO[ni][0]*inv0, accO[ni][1]*inv0);
        *(__half2*)(Oh + base + (size_t)(gr0+8)*DM + ni*8 + cc) =
            __floats2half2_rn(accO[ni][2]*inv1, accO[ni][3]*inv1);
    }
}

// ---------------------------------------------------------------------------
// LayerNorm (512). One block/row. Writes fp32 out and optional fp16 copy.
// ---------------------------------------------------------------------------
__global__ __launch_bounds__(128)
void ln_kernel(const float* __restrict__ in, const float* __restrict__ gamma,
               const float* __restrict__ beta, float* __restrict__ out,
               __half* __restrict__ out16)
{
    const int row = blockIdx.x, tid = threadIdx.x;
    const float4 v = ((const float4*)(in + (size_t)row*DM))[tid];
    float s  = v.x + v.y + v.z + v.w;
    float sq = v.x*v.x + v.y*v.y + v.z*v.z + v.w*v.w;
#pragma unroll
    for (int o = 16; o; o >>= 1) {
        s  += __shfl_down_sync(0xffffffffu, s,  o);
        sq += __shfl_down_sync(0xffffffffu, sq, o);
    }
    __shared__ float ss[4], sqs[4];
    const int w = tid >> 5, lane = tid & 31;
    if (lane == 0) { ss[w] = s; sqs[w] = sq; }
    __syncthreads();
    s  = ss[0] + ss[1] + ss[2] + ss[3];
    sq = sqs[0] + sqs[1] + sqs[2] + sqs[3];

    const float mean = s * (1.f / DM);
    const float var  = sq * (1.f / DM) - mean * mean;
    const float inv  = rsqrtf(var + LN_EPS);

    const float4 g4 = ((const float4*)gamma)[tid];
    const float4 b4 = ((const float4*)beta)[tid];
    float4 o4;
    o4.x = (v.x - mean)*inv*g4.x + b4.x;
    o4.y = (v.y - mean)*inv*g4.y + b4.y;
    o4.z = (v.z - mean)*inv*g4.z + b4.z;
    o4.w = (v.w - mean)*inv*g4.w + b4.w;
    ((float4*)(out + (size_t)row*DM))[tid] = o4;
    if (out16) {
        uint2 h;
        h.x = f2h2(o4.x, o4.y);
        h.y = f2h2(o4.z, o4.w);
        ((uint2*)(out16 + (size_t)row*DM))[tid] = h;
    }
}

// ---------------------------------------------------------------------------
extern "C" void kernel_launch(void* const* d_in, const int* in_sizes, int n_in,
                              void* d_out, int out_size)
{
    const float* x   = (const float*)d_in[0];
    const float* Wq  = (const float*)d_in[1];
    const float* bq  = (const float*)d_in[2];
    const float* Wk  = (const float*)d_in[3];
    const float* bk  = (const float*)d_in[4];
    const float* Wv  = (const float*)d_in[5];
    const float* bv  = (const float*)d_in[6];
    const float* Wo  = (const float*)d_in[7];
    const float* bo  = (const float*)d_in[8];
    const float* W1  = (const float*)d_in[9];
    const float* b1  = (const float*)d_in[10];
    const float* W2  = (const float*)d_in[11];
    const float* b2  = (const float*)d_in[12];
    const float* g1  = (const float*)d_in[13];
    const float* be1 = (const float*)d_in[14];
    const float* g2  = (const float*)d_in[15];
    const float* be2 = (const float*)d_in[16];

    __half *qh, *kh, *vth, *oh, *xh, *h1h, *ffh;
    __half *wqh, *wkh, *wvh, *woh, *w1h, *w2h;
    float *hb, *h1, *h2, *xb;
    cudaGetSymbolAddress((void**)&qh,  g_qh);
    cudaGetSymbolAddress((void**)&kh,  g_kh);
    cudaGetSymbolAddress((void**)&vth, g_vth);
    cudaGetSymbolAddress((void**)&oh,  g_oh);
    cudaGetSymbolAddress((void**)&xh,  g_xh);
    cudaGetSymbolAddress((void**)&h1h, g_h1h);
    cudaGetSymbolAddress((void**)&ffh, g_ffh);
    cudaGetSymbolAddress((void**)&hb,  g_h);
    cudaGetSymbolAddress((void**)&h1,  g_h1);
    cudaGetSymbolAddress((void**)&h2,  g_h2);
    cudaGetSymbolAddress((void**)&xb,  g_x);
    cudaGetSymbolAddress((void**)&wqh, g_wq);
    cudaGetSymbolAddress((void**)&wkh, g_wk);
    cudaGetSymbolAddress((void**)&wvh, g_wv);
    cudaGetSymbolAddress((void**)&woh, g_wo);
    cudaGetSymbolAddress((void**)&w1h, g_w1);
    cudaGetSymbolAddress((void**)&w2h, g_w2);

    cudaFuncSetAttribute(attn_f16, cudaFuncAttributeMaxDynamicSharedMemorySize,
                         AT_SMEM_BYTES);
    cudaFuncSetAttribute(gemm_h<1>, cudaFuncAttributeMaxDynamicSharedMemorySize,
                         GSMEM_BYTES);
    cudaFuncSetAttribute(gemm_h<2>, cudaFuncAttributeMaxDynamicSharedMemorySize,
                         GSMEM_BYTES);
    cudaFuncSetAttribute(gemm_qkv, cudaFuncAttributeMaxDynamicSharedMemorySize,
                         GSMEM_BYTES);

    // ---- one launch: fp32 -> fp16 for 6 weight arrays + layer-0 input ----
    {
        const int nqkv = NLAYERS*DM*DM/4;
        const int nff  = NLAYERS*DM*DFF/4;
        const int nx   = ROWS*DM/4;
        const int maxb = (nff + 255) / 256;
        dim3 g(maxb, 7);
        f2h_all<<<g, 256>>>((const float4*)Wq, (uint2*)wqh, nqkv,
                            (const float4*)Wk, (uint2*)wkh, nqkv,
                            (const float4*)Wv, (uint2*)wvh, nqkv,
                            (const float4*)Wo, (uint2*)woh, nqkv,
                            (const float4*)W1, (uint2*)w1h, nff,
                            (const float4*)W2, (uint2*)w2h, nff,
                            (const float4*)x,  (uint2*)xh,  nx);
    }

    const dim3 gQKV(12, ROWS / 256);           // (12, 32)
    const dim3 gProj(DM / 128, ROWS / 256);    // (4, 32)
    const dim3 gFF1 (DFF / 128, ROWS / 256);   // (16, 32)
    const dim3 gAttn(SEQ / 64, NHEAD, NB);     // (16, 8, 8)

    const float* hin = x;
    for (int l = 0; l < NLAYERS; l++) {
        const __half* wq = wqh + (size_t)l*DM*DM;
        const __half* wk = wkh + (size_t)l*DM*DM;
        const __half* wv = wvh + (size_t)l*DM*DM;
        const __half* wo = woh + (size_t)l*DM*DM;
        const __half* w1 = w1h + (size_t)l*DM*DFF;
        const __half* w2 = w2h + (size_t)l*DFF*DM;

        gemm_qkv<<<gQKV, 256, GSMEM_BYTES>>>(xh, wq, wk, wv,
                                             bq + l*DM, bk + l*DM, bv + l*DM,
                                             qh, kh, vth);

        attn_f16<<<gAttn, 128, AT_SMEM_BYTES>>>(qh, kh, vth, oh);

        gemm_h<2><<<gProj, 256, GSMEM_BYTES>>>(oh, wo, bo + l*DM, hin, hb,
                                               ROWS, DM, DM);
        ln_kernel<<<ROWS, 128>>>(hb, g1 + l*DM, be1 + l*DM, h1, h1h);

        gemm_h<1><<<gFF1, 256, GSMEM_BYTES>>>(h1h, w1, b1 + l*DFF, nullptr, ffh,
                                              ROWS, DFF, DM);
        gemm_h<2><<<gProj, 256, GSMEM_BYTES>>>(ffh, w2, b2 + l*DM, h1, h2,
                                               ROWS, DM, DFF);

        float* lnout = (l == NLAYERS - 1) ? (float*)d_out : xb;
        __half* lnout16 = (l == NLAYERS - 1) ? (__half*)nullptr : xh;
        ln_kernel<<<ROWS, 128>>>(h2, g2 + l*DM, be2 + l*DM, lnout, lnout16);
        hin = xb;
    }
}

// round 12
// speedup vs baseline: 1.0390x; 1.0390x over previous
#include <cuda_runtime.h>
#include <cuda_fp16.h>
#include <cstdint>
#include <cstddef>

// Problem constants
#define DM      512
#define DFF     2048
#define NB      8
#define SEQ     1024
#define NHEAD   8
#define EHEAD   64
#define ROWS    (NB*SEQ)     // 8192
#define NLAYERS 4
#define LN_EPS  1e-5f

// ---------------- scratch (device globals; no allocations allowed) --------
__device__ __half g_qh [ROWS*DM];    // Q (pre-scaled 1/8)
__device__ __half g_kh [ROWS*DM];
__device__ __half g_vth[DM*ROWS];    // V^T [col][token]
__device__ __half g_oh [ROWS*DM];    // attention out
__device__ __half g_xh [ROWS*DM];    // fp16 copy of layer input
__device__ __half g_h1h[ROWS*DM];    // fp16 copy of post-LN1
__device__ __half g_ffh[ROWS*DFF];   // ReLU(FFN1) in fp16
__device__ float  g_h  [ROWS*DM];
__device__ float  g_h1 [ROWS*DM];
__device__ float  g_h2 [ROWS*DM];
__device__ float  g_x  [ROWS*DM];
// fp16 weights (converted once per launch)
__device__ __half g_wq[NLAYERS*DM*DM];
__device__ __half g_wk[NLAYERS*DM*DM];
__device__ __half g_wv[NLAYERS*DM*DM];
__device__ __half g_wo[NLAYERS*DM*DM];
__device__ __half g_w1[NLAYERS*DM*DFF];
__device__ __half g_w2[NLAYERS*DFF*DM];

// ---------------- helpers ---------------------------------------------------
__device__ __forceinline__ uint32_t f2h2(float a, float b) {
    __half2 h = __floats2half2_rn(a, b);
    return *(uint32_t*)&h;
}
__device__ __forceinline__ void ldsm4(uint32_t* r, uint32_t addr) {
    asm volatile("ldmatrix.sync.aligned.m8n8.x4.shared.b16 {%0,%1,%2,%3}, [%4];\n"
                 : "=r"(r[0]), "=r"(r[1]), "=r"(r[2]), "=r"(r[3]) : "r"(addr));
}
__device__ __forceinline__ void ldsm4t(uint32_t* r, uint32_t addr) {
    asm volatile("ldmatrix.sync.aligned.m8n8.x4.trans.shared.b16 {%0,%1,%2,%3}, [%4];\n"
                 : "=r"(r[0]), "=r"(r[1]), "=r"(r[2]), "=r"(r[3]) : "r"(addr));
}
__device__ __forceinline__ void mma_f16(float* d, const uint32_t* a,
                                        uint32_t b0, uint32_t b1) {
    asm volatile(
        "mma.sync.aligned.m16n8k16.row.col.f32.f16.f16.f32 "
        "{%0,%1,%2,%3},{%4,%5,%6,%7},{%8,%9},{%0,%1,%2,%3};\n"
        : "+f"(d[0]), "+f"(d[1]), "+f"(d[2]), "+f"(d[3])
        : "r"(a[0]), "r"(a[1]), "r"(a[2]), "r"(a[3]), "r"(b0), "r"(b1));
}
__device__ __forceinline__ uint32_t smem_u32(const void* p) {
    return (uint32_t)__cvta_generic_to_shared(p);
}
__device__ __forceinline__ void cpa16(uint32_t dst, const void* src) {
    asm volatile("cp.async.ca.shared.global [%0], [%1], 16;\n"
                 :: "r"(dst), "l"(src) : "memory");
}
__device__ __forceinline__ void cpa_commit() {
    asm volatile("cp.async.commit_group;\n" ::: "memory");
}
template<int N>
__device__ __forceinline__ void cpa_wait() {
    asm volatile("cp.async.wait_group %0;\n" :: "n"(N) : "memory");
}

// ---------------- fp32 -> fp16 bulk convert (all 7 arrays, one launch) -----
__global__ __launch_bounds__(256)
void f2h_all(const float4* s0, uint2* d0, int n0,
             const float4* s1, uint2* d1, int n1,
             const float4* s2, uint2* d2, int n2,
             const float4* s3, uint2* d3, int n3,
             const float4* s4, uint2* d4, int n4,
             const float4* s5, uint2* d5, int n5,
             const float4* s6, uint2* d6, int n6)
{
    const float4* s; uint2* d; int n;
    switch (blockIdx.y) {
        case 0: s = s0; d = d0; n = n0; break;
        case 1: s = s1; d = d1; n = n1; break;
        case 2: s = s2; d = d2; n = n2; break;
        case 3: s = s3; d = d3; n = n3; break;
        case 4: s = s4; d = d4; n = n4; break;
        case 5: s = s5; d = d5; n = n5; break;
        default: s = s6; d = d6; n = n6; break;
    }
    int i = blockIdx.x*blockDim.x + threadIdx.x;
    if (i < n) {
        float4 v = s[i];
        uint2 o;
        o.x = f2h2(v.x, v.y);
        o.y = f2h2(v.z, v.w);
        d[i] = o;
    }
}

// ---------------------------------------------------------------------------
// GEMM core: BM=BN=128, BK=32, 256 thr (8 warps, 4m x 2n, warp tile 32x64),
// m16n8k16, 5-stage cp.async ring in dynamic smem, one __syncthreads/k-tile.
// ---------------------------------------------------------------------------
#define GPA 40
#define GPB 136
#define ABUF (128*GPA)            // halfs per A stage (5120)
#define BBUF (32*GPB)             // halfs per B stage (4352)
#define GSTAGES 5
#define GSMEM_BYTES (GSTAGES*(ABUF+BBUF)*2)   // 94720 B

// issue one k-tile's cp.async into stage st
#define GEMM_ISSUE(Aptr, Bptr, Kdim, Ndim, st, k0)                              \
    {                                                                           \
        const uint32_t oA = (uint32_t)((st)*ABUF*2);                            \
        const uint32_t oB = (uint32_t)((st)*BBUF*2);                            \
        cpa16(sAu + oA + dA0, (Aptr) + (size_t)ar0*(Kdim) + (k0) + ak0);        \
        cpa16(sAu + oA + dA1, (Aptr) + (size_t)ar1*(Kdim) + (k0) + ak1);        \
        cpa16(sBu + oB + dB0, (Bptr) + (size_t)((k0) + bk0)*(Ndim) + bn0);      \
        cpa16(sBu + oB + dB1, (Bptr) + (size_t)((k0) + bk1)*(Ndim) + bn0);      \
    }

#define GEMM_MAINLOOP(Aptr, Bptr, Kdim, Ndim)                                   \
    __half* smA = dsm;                                                          \
    __half* smB = dsm + GSTAGES*ABUF;                                           \
    const int ar0 = tid >> 2,         ak0 = (tid & 3) << 3;                     \
    const int ar1 = (tid + 256) >> 2, ak1 = ((tid + 256) & 3) << 3;             \
    const int bk0 = tid >> 4,         bn0 = (tid & 15) << 3;                    \
    const int bk1 = bk0 + 16;                                                   \
    const uint32_t sAu = smem_u32(smA);                                         \
    const uint32_t sBu = smem_u32(smB);                                         \
    const uint32_t dA0 = (uint32_t)((ar0*GPA + ak0) << 1);                      \
    const uint32_t dA1 = (uint32_t)((ar1*GPA + ak1) << 1);                      \
    const uint32_t dB0 = (uint32_t)((bk0*GPB + bn0) << 1);                      \
    const uint32_t dB1 = (uint32_t)((bk1*GPB + bn0) << 1);                      \
    uint32_t aAd[2], bAd[4];                                                    \
    _Pragma("unroll")                                                           \
    for (int mi = 0; mi < 2; mi++)                                              \
        aAd[mi] = sAu + (((wm*32 + mi*16 + (lane & 15))*GPA + (lane >> 4)*8) << 1); \
    _Pragma("unroll")                                                           \
    for (int nt = 0; nt < 4; nt++)                                              \
        bAd[nt] = sBu + ((((lane & 7) + ((lane >> 3) & 1)*8)*GPB                \
                          + wn*64 + nt*16 + (lane >> 4)*8) << 1);               \
    float acc[2][8][4];                                                         \
    _Pragma("unroll")                                                           \
    for (int mi = 0; mi < 2; mi++)                                              \
        _Pragma("unroll")                                                       \
        for (int ni = 0; ni < 8; ni++)                                          \
            _Pragma("unroll")                                                   \
            for (int c = 0; c < 4; c++) acc[mi][ni][c] = 0.f;                   \
    const int KT = (Kdim) >> 5;                                                 \
    GEMM_ISSUE(Aptr, Bptr, Kdim, Ndim, 0, 0)   cpa_commit();                    \
    GEMM_ISSUE(Aptr, Bptr, Kdim, Ndim, 1, 32)  cpa_commit();                    \
    GEMM_ISSUE(Aptr, Bptr, Kdim, Ndim, 2, 64)  cpa_commit();                    \
    GEMM_ISSUE(Aptr, Bptr, Kdim, Ndim, 3, 96)  cpa_commit();                    \
    int st = 0, rs = GSTAGES - 1;                                               \
    for (int kt = 0; kt < KT; kt++) {                                           \
        cpa_wait<GSTAGES - 2>();                                                \
        __syncthreads();                                                        \
        if (kt + GSTAGES - 1 < KT) {                                            \
            GEMM_ISSUE(Aptr, Bptr, Kdim, Ndim, rs, (kt + GSTAGES - 1)*32)       \
        }                                                                       \
        cpa_commit();                                                           \
        const uint32_t boA = (uint32_t)(st*ABUF*2);                             \
        const uint32_t boB = (uint32_t)(st*BBUF*2);                             \
        _Pragma("unroll")                                                       \
        for (int kh = 0; kh < 2; kh++) {                                        \
            uint32_t af[2][4], bf[4][4];                                        \
            ldsm4(af[0], aAd[0] + boA + kh*32);                                 \
            ldsm4(af[1], aAd[1] + boA + kh*32);                                 \
            _Pragma("unroll")                                                   \
            for (int nt = 0; nt < 4; nt++)                                      \
                ldsm4t(bf[nt], bAd[nt] + boB + kh*16*GPB*2);                    \
            _Pragma("unroll")                                                   \
            for (int nt = 0; nt < 4; nt++) {                                    \
                _Pragma("unroll")                                               \
                for (int mi = 0; mi < 2; mi++) {                                \
                    mma_f16(acc[mi][2*nt],   af[mi], bf[nt][0], bf[nt][1]);     \
                    mma_f16(acc[mi][2*nt+1], af[mi], bf[nt][2], bf[nt][3]);     \
                }                                                               \
            }                                                                   \
        }                                                                       \
        st = (st + 1 == GSTAGES) ? 0 : st + 1;                                  \
        rs = (rs + 1 == GSTAGES) ? 0 : rs + 1;                                  \
    }

// ---------------------------------------------------------------------------
// General fp16 GEMM with fused epilogues.
//  EPI 1: half out, bias+relu   EPI 2: f32 out, bias+residual
// ---------------------------------------------------------------------------
template<int EPI>
__global__ __launch_bounds__(256, 2)
void gemm_h(const __half* __restrict__ A, const __half* __restrict__ B,
            const float* __restrict__ bias, const float* __restrict__ res,
            void* __restrict__ Cv, int M, int N, int K)
{
    extern __shared__ __half dsm[];

    const int tid = threadIdx.x;
    const int lane = tid & 31, wid = tid >> 5;
    const int wm = wid & 3, wn = wid >> 2;
    const int bx = blockIdx.x, by = blockIdx.y;

    const __half* Ag = A + (size_t)(by*128)*K;
    const __half* Bg = B + (size_t)bx*128;

    GEMM_MAINLOOP(Ag, Bg, K, N)

    const int r0 = (by*128) + wm*32 + (lane >> 2);
#pragma unroll
    for (int mi = 0; mi < 2; mi++) {
        const int gr = r0 + mi*16;
#pragma unroll
        for (int ni = 0; ni < 8; ni++) {
            const int gc = (bx*128) + wn*64 + (ni >> 1)*16 + (ni & 1)*8
                         + ((lane & 3) << 1);
            const float2 bia = *(const float2*)(bias + gc);
            float2 v0 = make_float2(acc[mi][ni][0] + bia.x, acc[mi][ni][1] + bia.y);
            float2 v1 = make_float2(acc[mi][ni][2] + bia.x, acc[mi][ni][3] + bia.y);
            if (EPI == 1) {
                v0.x = fmaxf(v0.x, 0.f); v0.y = fmaxf(v0.y, 0.f);
                v1.x = fmaxf(v1.x, 0.f); v1.y = fmaxf(v1.y, 0.f);
                __half* Ch = (__half*)Cv;
                *(__half2*)(Ch + (size_t)gr*N + gc)     = __floats2half2_rn(v0.x, v0.y);
                *(__half2*)(Ch + (size_t)(gr+8)*N + gc) = __floats2half2_rn(v1.x, v1.y);
            } else {  // EPI == 2
                const float2 r_0 = *(const float2*)(res + (size_t)gr*N + gc);
                const float2 r_1 = *(const float2*)(res + (size_t)(gr+8)*N + gc);
                v0.x += r_0.x; v0.y += r_0.y;
                v1.x += r_1.x; v1.y += r_1.y;
                float* Cf = (float*)Cv;
                *(float2*)(Cf + (size_t)gr*N + gc)     = v0;
                *(float2*)(Cf + (size_t)(gr+8)*N + gc) = v1;
            }
        }
    }
}

// ---------------------------------------------------------------------------
// Fused QKV projection: grid (12, 64). bx>>2 selects Q/K/V.
// ---------------------------------------------------------------------------
__global__ __launch_bounds__(256, 2)
void gemm_qkv(const __half* __restrict__ A,
              const __half* __restrict__ Bq, const __half* __restrict__ Bk,
              const __half* __restrict__ Bv,
              const float* __restrict__ bq, const float* __restrict__ bk,
              const float* __restrict__ bv,
              __half* __restrict__ Oq, __half* __restrict__ Ok,
              __half* __restrict__ Ovt)
{
    extern __shared__ __half dsm[];

    const int tid = threadIdx.x;
    const int lane = tid & 31, wid = tid >> 5;
    const int wm = wid & 3, wn = wid >> 2;
    const int sel = blockIdx.x >> 2, bx = blockIdx.x & 3;
    const int by = blockIdx.y;
    const int N = DM, K = DM;

    const __half* B  = (sel == 0) ? Bq : (sel == 1) ? Bk : Bv;
    const float* bia_p = (sel == 0) ? bq : (sel == 1) ? bk : bv;

    const __half* Ag = A + (size_t)(by*128)*K;
    const __half* Bg = B + (size_t)bx*128;

    GEMM_MAINLOOP(Ag, Bg, K, N)

    const int r0 = (by*128) + wm*32 + (lane >> 2);
#pragma unroll
    for (int mi = 0; mi < 2; mi++) {
        const int gr = r0 + mi*16;
#pragma unroll
        for (int ni = 0; ni < 8; ni++) {
            const int gc = (bx*128) + wn*64 + (ni >> 1)*16 + (ni & 1)*8
                         + ((lane & 3) << 1);
            const float2 bia = *(const float2*)(bia_p + gc);
            float2 v0 = make_float2(acc[mi][ni][0] + bia.x, acc[mi][ni][1] + bia.y);
            float2 v1 = make_float2(acc[mi][ni][2] + bia.x, acc[mi][ni][3] + bia.y);
            if (sel == 0) {
                *(__half2*)(Oq + (size_t)gr*N + gc) =
                    __floats2half2_rn(v0.x*0.125f, v0.y*0.125f);
                *(__half2*)(Oq + (size_t)(gr+8)*N + gc) =
                    __floats2half2_rn(v1.x*0.125f, v1.y*0.125f);
            } else if (sel == 1) {
                *(__half2*)(Ok + (size_t)gr*N + gc)     = __floats2half2_rn(v0.x, v0.y);
                *(__half2*)(Ok + (size_t)(gr+8)*N + gc) = __floats2half2_rn(v1.x, v1.y);
            } else {
                Ovt[(size_t)gc*ROWS + gr]         = __float2half_rn(v0.x);
                Ovt[(size_t)(gc+1)*ROWS + gr]     = __float2half_rn(v0.y);
                Ovt[(size_t)gc*ROWS + gr + 8]     = __float2half_rn(v1.x);
                Ovt[(size_t)(gc+1)*ROWS + gr + 8] = __float2half_rn(v1.y);
            }
        }
    }
}

// ---------------------------------------------------------------------------
// FP16 flash attention, 64 q-rows / 128 threads / 4 warps per CTA,
// 2 CTAs per SM. K-tile 128 keys double-buffered; V from V^T. (R10 version)
// ---------------------------------------------------------------------------
#define AT_PA 136
#define AT_PK 72
#define AT_AH (64*AT_PA)
#define AT_KH (128*AT_PK)
#define AT_VH (64*AT_PA)
#define AT_OFF_K AT_AH
#define AT_OFF_V (AT_OFF_K + 2*AT_KH)
#define AT_SMEM_BYTES ((AT_OFF_V + 2*AT_VH)*2)   // 89088 B

__global__ __launch_bounds__(128, 2)
void attn_f16(const __half* __restrict__ Qh, const __half* __restrict__ Kh,
              const __half* __restrict__ Vth, __half* __restrict__ Oh)
{
    extern __shared__ __half smh[];
    __half* sA = smh;

    const int n = blockIdx.z, h = blockIdx.y;
    const int tid = threadIdx.x, lane = tid & 31, w = tid >> 5;
    const size_t base  = ((size_t)n*SEQ)*DM + h*EHEAD;
    const size_t vbase = ((size_t)h*EHEAD)*ROWS + (size_t)n*SEQ;
    const int q0 = blockIdx.x * 64;

    const uint32_t sAu = smem_u32(sA);
    const uint32_t sKu = smem_u32(smh + AT_OFF_K);
    const uint32_t sVu = smem_u32(smh + AT_OFF_V);

#pragma unroll
    for (int j = 0; j < 4; j++) {
        int idx = j*128 + tid;
        int r = idx >> 3, c8 = (idx & 7) << 3;
        cpa16(sAu + (uint32_t)((r*AT_PA + c8) << 1),
              Qh + base + (size_t)(q0 + r)*DM + c8);
    }
    cpa_commit();
#pragma unroll
    for (int j = 0; j < 8; j++) {
        int idx = j*128 + tid;
        int r = idx >> 3, c8 = (idx & 7) << 3;
        cpa16(sKu + (uint32_t)((r*AT_PK + c8) << 1),
              Kh + base + (size_t)r*DM + c8);
    }
#pragma unroll
    for (int j = 0; j < 8; j++) {
        int idx = j*128 + tid;
        int r = idx >> 4, c8 = (idx & 15) << 3;
        cpa16(sVu + (uint32_t)((r*AT_PA + c8) << 1),
              Vth + vbase + (size_t)r*ROWS + c8);
    }
    cpa_commit();

    cpa_wait<1>();
    __syncthreads();

    const uint32_t aBase = sAu + (((w*16 + (lane & 15))*AT_PA + (lane >> 4)*8) << 1);
    uint32_t aQ[4][4];
#pragma unroll
    for (int ks = 0; ks < 4; ks++) ldsm4(aQ[ks], aBase + ks*32);

    uint32_t bK[8], bV[4];
#pragma unroll
    for (int p = 0; p < 8; p++)
        bK[p] = sKu + (((p*16 + (lane & 7) + ((lane >> 3) & 1)*8)*AT_PK
                        + (lane >> 4)*8) << 1);
#pragma unroll
    for (int p = 0; p < 4; p++)
        bV[p] = sVu + (((p*16 + (lane & 7) + ((lane >> 3) & 1)*8)*AT_PA
                        + (lane >> 4)*8) << 1);

    float accO[8][4];
#pragma unroll
    for (int ni = 0; ni < 8; ni++)
#pragma unroll
        for (int c = 0; c < 4; c++) accO[ni][c] = 0.f;
    float m0 = -1e30f, m1 = -1e30f, l0 = 0.f, l1 = 0.f;

    const int rA = w*16 + (lane >> 2);
    __half* pr0 = &sA[rA*AT_PA + 2*(lane & 3)];
    __half* pr1 = pr0 + 8*AT_PA;

    for (int kt = 0; kt < SEQ/128; kt++) {
        const int buf = kt & 1;
        if (kt + 1 < SEQ/128) {
            const int nb = buf ^ 1;
            const uint32_t ko = (uint32_t)(nb * AT_KH) << 1;
            const uint32_t vo = (uint32_t)(nb * AT_VH) << 1;
#pragma unroll
            for (int j = 0; j < 8; j++) {
                int idx = j*128 + tid;
                int r = idx >> 3, c8 = (idx & 7) << 3;
                cpa16(sKu + ko + (uint32_t)((r*AT_PK + c8) << 1),
                      Kh + base + (size_t)((kt+1)*128 + r)*DM + c8);
            }
#pragma unroll
            for (int j = 0; j < 8; j++) {
                int idx = j*128 + tid;
                int r = idx >> 4, c8 = (idx & 15) << 3;
                cpa16(sVu + vo + (uint32_t)((r*AT_PA + c8) << 1),
                      Vth + vbase + (size_t)r*ROWS + (kt+1)*128 + c8);
            }
            cpa_commit();
            cpa_wait<1>();
        } else {
            cpa_wait<0>();
        }
        __syncthreads();

        const uint32_t ko = (uint32_t)(buf * AT_KH) << 1;
        const uint32_t vo = (uint32_t)(buf * AT_VH) << 1;

        float accS[16][4];
#pragma unroll
        for (int t = 0; t < 16; t++)
#pragma unroll
            for (int c = 0; c < 4; c++) accS[t][c] = 0.f;
#pragma unroll
        for (int ks = 0; ks < 4; ks++) {
#pragma unroll
            for (int p = 0; p < 8; p++) {
                uint32_t bf[4];
                ldsm4(bf, bK[p] + ko + ks*32);
                mma_f16(accS[2*p],   aQ[ks], bf[0], bf[2]);
                mma_f16(accS[2*p+1], aQ[ks], bf[1], bf[3]);
            }
        }

        float rmax0 = -1e30f, rmax1 = -1e30f;
#pragma unroll
        for (int t = 0; t < 16; t++) {
            rmax0 = fmaxf(rmax0, fmaxf(accS[t][0], accS[t][1]));
            rmax1 = fmaxf(rmax1, fmaxf(accS[t][2], accS[t][3]));
        }
        rmax0 = fmaxf(rmax0, __shfl_xor_sync(0xffffffffu, rmax0, 1));
        rmax0 = fmaxf(rmax0, __shfl_xor_sync(0xffffffffu, rmax0, 2));
        rmax1 = fmaxf(rmax1, __shfl_xor_sync(0xffffffffu, rmax1, 1));
        rmax1 = fmaxf(rmax1, __shfl_xor_sync(0xffffffffu, rmax1, 2));
        const float mn0 = fmaxf(m0, rmax0), mn1 = fmaxf(m1, rmax1);
        const float cr0 = __expf(m0 - mn0), cr1 = __expf(m1 - mn1);
        m0 = mn0; m1 = mn1;
        l0 *= cr0; l1 *= cr1;
#pragma unroll
        for (int ni = 0; ni < 8; ni++) {
            accO[ni][0] *= cr0; accO[ni][1] *= cr0;
            accO[ni][2] *= cr1; accO[ni][3] *= cr1;
        }
#pragma unroll
        for (int t = 0; t < 16; t++) {
            float p0 = __expf(accS[t][0] - m0), p1 = __expf(accS[t][1] - m0);
            float p2 = __expf(accS[t][2] - m1), p3 = __expf(accS[t][3] - m1);
            l0 += p0 + p1; l1 += p2 + p3;
            *(__half2*)(pr0 + t*8) = __floats2half2_rn(p0, p1);
            *(__half2*)(pr1 + t*8) = __floats2half2_rn(p2, p3);
        }
        __syncwarp();

#pragma unroll
        for (int ks = 0; ks < 8; ks++) {
            uint32_t aP[4];
            ldsm4(aP, aBase + ks*32);
#pragma unroll
            for (int p = 0; p < 4; p++) {
                uint32_t bf[4];
                ldsm4(bf, bV[p] + vo + ks*32);
                mma_f16(accO[2*p],   aP, bf[0], bf[2]);
                mma_f16(accO[2*p+1], aP, bf[1], bf[3]);
            }
        }
        __syncthreads();
    }

    l0 += __shfl_xor_sync(0xffffffffu, l0, 1);
    l0 += __shfl_xor_sync(0xffffffffu, l0, 2);
    l1 += __shfl_xor_sync(0xffffffffu, l1, 1);
    l1 += __shfl_xor_sync(0xffffffffu, l1, 2);
    const float inv0 = 1.f / l0, inv1 = 1.f / l1;
    const int gr0 = q0 + w*16 + (lane >> 2);
    const int cc = 2*(lane & 3);
#pragma unroll
    for (int ni = 0; ni < 8; ni++) {
        *(__half2*)(Oh + base + (size_t)gr0*DM + ni*8 + cc) =
            __floats2half2_rn(accO[ni][0]*inv0, accO[ni][1]*inv0);
        *(__half2*)(Oh + base + (size_t)(gr0+8)*DM + ni*8 + cc) =
            __floats2half2_rn(accO[ni][2]*inv1, accO[ni][3]*inv1);
    }
}

// ---------------------------------------------------------------------------
// LayerNorm (512): one WARP per row, 256 threads = 8 rows/CTA, shfl-only.
// ---------------------------------------------------------------------------
__global__ __launch_bounds__(256)
void ln_kernel(const float* __restrict__ in, const float* __restrict__ gamma,
               const float* __restrict__ beta, float* __restrict__ out,
               __half* __restrict__ out16)
{
    const int w = threadIdx.x >> 5, lane = threadIdx.x & 31;
    const int row = blockIdx.x*8 + w;
    const float4* p = (const float4*)(in + (size_t)row*DM);

    float4 v[4];
    float s = 0.f, sq = 0.f;
#pragma unroll
    for (int i = 0; i < 4; i++) {
        v[i] = p[lane + 32*i];
        s  += v[i].x + v[i].y + v[i].z + v[i].w;
        sq += v[i].x*v[i].x + v[i].y*v[i].y + v[i].z*v[i].z + v[i].w*v[i].w;
    }
#pragma unroll
    for (int o = 16; o; o >>= 1) {
        s  += __shfl_xor_sync(0xffffffffu, s,  o);
        sq += __shfl_xor_sync(0xffffffffu, sq, o);
    }
    const float mean = s * (1.f / DM);
    const float var  = sq * (1.f / DM) - mean * mean;
    const float inv  = rsqrtf(var + LN_EPS);

    float4* op = (float4*)(out + (size_t)row*DM);
    uint2*  hp = out16 ? (uint2*)(out16 + (size_t)row*DM) : nullptr;
#pragma unroll
    for (int i = 0; i < 4; i++) {
        const float4 g4 = ((const float4*)gamma)[lane + 32*i];
        const float4 b4 = ((const float4*)beta)[lane + 32*i];
        float4 o4;
        o4.x = (v[i].x - mean)*inv*g4.x + b4.x;
        o4.y = (v[i].y - mean)*inv*g4.y + b4.y;
        o4.z = (v[i].z - mean)*inv*g4.z + b4.z;
        o4.w = (v[i].w - mean)*inv*g4.w + b4.w;
        op[lane + 32*i] = o4;
        if (hp) {
            uint2 h;
            h.x = f2h2(o4.x, o4.y);
            h.y = f2h2(o4.z, o4.w);
            hp[lane + 32*i] = h;
        }
    }
}

// ---------------------------------------------------------------------------
extern "C" void kernel_launch(void* const* d_in, const int* in_sizes, int n_in,
                              void* d_out, int out_size)
{
    const float* x   = (const float*)d_in[0];
    const float* Wq  = (const float*)d_in[1];
    const float* bq  = (const float*)d_in[2];
    const float* Wk  = (const float*)d_in[3];
    const float* bk  = (const float*)d_in[4];
    const float* Wv  = (const float*)d_in[5];
    const float* bv  = (const float*)d_in[6];
    const float* Wo  = (const float*)d_in[7];
    const float* bo  = (const float*)d_in[8];
    const float* W1  = (const float*)d_in[9];
    const float* b1  = (const float*)d_in[10];
    const float* W2  = (const float*)d_in[11];
    const float* b2  = (const float*)d_in[12];
    const float* g1  = (const float*)d_in[13];
    const float* be1 = (const float*)d_in[14];
    const float* g2  = (const float*)d_in[15];
    const float* be2 = (const float*)d_in[16];

    __half *qh, *kh, *vth, *oh, *xh, *h1h, *ffh;
    __half *wqh, *wkh, *wvh, *woh, *w1h, *w2h;
    float *hb, *h1, *h2, *xb;
    cudaGetSymbolAddress((void**)&qh,  g_qh);
    cudaGetSymbolAddress((void**)&kh,  g_kh);
    cudaGetSymbolAddress((void**)&vth, g_vth);
    cudaGetSymbolAddress((void**)&oh,  g_oh);
    cudaGetSymbolAddress((void**)&xh,  g_xh);
    cudaGetSymbolAddress((void**)&h1h, g_h1h);
    cudaGetSymbolAddress((void**)&ffh, g_ffh);
    cudaGetSymbolAddress((void**)&hb,  g_h);
    cudaGetSymbolAddress((void**)&h1,  g_h1);
    cudaGetSymbolAddress((void**)&h2,  g_h2);
    cudaGetSymbolAddress((void**)&xb,  g_x);
    cudaGetSymbolAddress((void**)&wqh, g_wq);
    cudaGetSymbolAddress((void**)&wkh, g_wk);
    cudaGetSymbolAddress((void**)&wvh, g_wv);
    cudaGetSymbolAddress((void**)&woh, g_wo);
    cudaGetSymbolAddress((void**)&w1h, g_w1);
    cudaGetSymbolAddress((void**)&w2h, g_w2);

    cudaFuncSetAttribute(attn_f16, cudaFuncAttributeMaxDynamicSharedMemorySize,
                         AT_SMEM_BYTES);
    cudaFuncSetAttribute(gemm_h<1>, cudaFuncAttributeMaxDynamicSharedMemorySize,
                         GSMEM_BYTES);
    cudaFuncSetAttribute(gemm_h<2>, cudaFuncAttributeMaxDynamicSharedMemorySize,
                         GSMEM_BYTES);
    cudaFuncSetAttribute(gemm_qkv, cudaFuncAttributeMaxDynamicSharedMemorySize,
                         GSMEM_BYTES);

    // ---- one launch: fp32 -> fp16 for 6 weight arrays + layer-0 input ----
    {
        const int nqkv = NLAYERS*DM*DM/4;
        const int nff  = NLAYERS*DM*DFF/4;
        const int nx   = ROWS*DM/4;
        const int maxb = (nff + 255) / 256;
        dim3 g(maxb, 7);
        f2h_all<<<g, 256>>>((const float4*)Wq, (uint2*)wqh, nqkv,
                            (const float4*)Wk, (uint2*)wkh, nqkv,
                            (const float4*)Wv, (uint2*)wvh, nqkv,
                            (const float4*)Wo, (uint2*)woh, nqkv,
                            (const float4*)W1, (uint2*)w1h, nff,
                            (const float4*)W2, (uint2*)w2h, nff,
                            (const float4*)x,  (uint2*)xh,  nx);
    }

    const dim3 gQKV(12, ROWS / 128);           // (12, 64) fused QKV
    const dim3 gProj(DM / 128, ROWS / 128);    // (4, 64)
    const dim3 gFF1 (DFF / 128, ROWS / 128);   // (16, 64)
    const dim3 gAttn(SEQ / 64, NHEAD, NB);     // (16, 8, 8)
    const dim3 gLN(ROWS / 8);                  // 1024 blocks, warp-per-row

    const float* hin = x;
    for (int l = 0; l < NLAYERS; l++) {
        const __half* wq = wqh + (size_t)l*DM*DM;
        const __half* wk = wkh + (size_t)l*DM*DM;
        const __half* wv = wvh + (size_t)l*DM*DM;
        const __half* wo = woh + (size_t)l*DM*DM;
        const __half* w1 = w1h + (size_t)l*DM*DFF;
        const __half* w2 = w2h + (size_t)l*DFF*DM;

        gemm_qkv<<<gQKV, 256, GSMEM_BYTES>>>(xh, wq, wk, wv,
                                             bq + l*DM, bk + l*DM, bv + l*DM,
                                             qh, kh, vth);

        attn_f16<<<gAttn, 128, AT_SMEM_BYTES>>>(qh, kh, vth, oh);

        gemm_h<2><<<gProj, 256, GSMEM_BYTES>>>(oh, wo, bo + l*DM, hin, hb,
                                               ROWS, DM, DM);
        ln_kernel<<<gLN, 256>>>(hb, g1 + l*DM, be1 + l*DM, h1, h1h);

        gemm_h<1><<<gFF1, 256, GSMEM_BYTES>>>(h1h, w1, b1 + l*DFF, nullptr, ffh,
                                              ROWS, DFF, DM);
        gemm_h<2><<<gProj, 256, GSMEM_BYTES>>>(ffh, w2, b2 + l*DM, h1, h2,
                                               ROWS, DM, DFF);

        float* lnout = (l == NLAYERS - 1) ? (float*)d_out : xb;
        __half* lnout16 = (l == NLAYERS - 1) ? (__half*)nullptr : xh;
        ln_kernel<<<gLN, 256>>>(h2, g2 + l*DM, be2 + l*DM, lnout, lnout16);
        hin = xb;
    }
}

// round 13
// speedup vs baseline: 1.0670x; 1.0269x over previous
#include <cuda_runtime.h>
#include <cuda_fp16.h>
#include <cstdint>
#include <cstddef>

// Problem constants
#define DM      512
#define DFF     2048
#define NB      8
#define SEQ     1024
#define NHEAD   8
#define EHEAD   64
#define ROWS    (NB*SEQ)     // 8192
#define NLAYERS 4
#define LN_EPS  1e-5f

// ---------------- scratch (device globals; no allocations allowed) --------
__device__ __half g_qh [ROWS*DM];    // Q (pre-scaled 1/8)
__device__ __half g_kh [ROWS*DM];
__device__ __half g_vth[DM*ROWS];    // V^T [col][token]
__device__ __half g_oh [ROWS*DM];    // attention out
__device__ __half g_xh [ROWS*DM];    // fp16 copy of layer input
__device__ __half g_h1h[ROWS*DM];    // fp16 copy of post-LN1
__device__ __half g_ffh[ROWS*DFF];   // ReLU(FFN1) in fp16
__device__ float  g_h  [ROWS*DM];
__device__ float  g_h1 [ROWS*DM];
__device__ float  g_h2 [ROWS*DM];
__device__ float  g_x  [ROWS*DM];
// fp16 weights (converted once per launch)
__device__ __half g_wq[NLAYERS*DM*DM];
__device__ __half g_wk[NLAYERS*DM*DM];
__device__ __half g_wv[NLAYERS*DM*DM];
__device__ __half g_wo[NLAYERS*DM*DM];
__device__ __half g_w1[NLAYERS*DM*DFF];
__device__ __half g_w2[NLAYERS*DFF*DM];

// ---------------- helpers ---------------------------------------------------
__device__ __forceinline__ uint32_t f2h2(float a, float b) {
    __half2 h = __floats2half2_rn(a, b);
    return *(uint32_t*)&h;
}
__device__ __forceinline__ void ldsm4(uint32_t* r, uint32_t addr) {
    asm volatile("ldmatrix.sync.aligned.m8n8.x4.shared.b16 {%0,%1,%2,%3}, [%4];\n"
                 : "=r"(r[0]), "=r"(r[1]), "=r"(r[2]), "=r"(r[3]) : "r"(addr));
}
__device__ __forceinline__ void ldsm4t(uint32_t* r, uint32_t addr) {
    asm volatile("ldmatrix.sync.aligned.m8n8.x4.trans.shared.b16 {%0,%1,%2,%3}, [%4];\n"
                 : "=r"(r[0]), "=r"(r[1]), "=r"(r[2]), "=r"(r[3]) : "r"(addr));
}
__device__ __forceinline__ void mma_f16(float* d, const uint32_t* a,
                                        uint32_t b0, uint32_t b1) {
    asm volatile(
        "mma.sync.aligned.m16n8k16.row.col.f32.f16.f16.f32 "
        "{%0,%1,%2,%3},{%4,%5,%6,%7},{%8,%9},{%0,%1,%2,%3};\n"
        : "+f"(d[0]), "+f"(d[1]), "+f"(d[2]), "+f"(d[3])
        : "r"(a[0]), "r"(a[1]), "r"(a[2]), "r"(a[3]), "r"(b0), "r"(b1));
}
__device__ __forceinline__ uint32_t smem_u32(const void* p) {
    return (uint32_t)__cvta_generic_to_shared(p);
}
__device__ __forceinline__ void cpa16(uint32_t dst, const void* src) {
    asm volatile("cp.async.ca.shared.global [%0], [%1], 16;\n"
                 :: "r"(dst), "l"(src) : "memory");
}
__device__ __forceinline__ void cpa_commit() {
    asm volatile("cp.async.commit_group;\n" ::: "memory");
}
template<int N>
__device__ __forceinline__ void cpa_wait() {
    asm volatile("cp.async.wait_group %0;\n" :: "n"(N) : "memory");
}

// ---------------- fp32 -> fp16 bulk convert (all 7 arrays, one launch) -----
__global__ __launch_bounds__(256)
void f2h_all(const float4* s0, uint2* d0, int n0,
             const float4* s1, uint2* d1, int n1,
             const float4* s2, uint2* d2, int n2,
             const float4* s3, uint2* d3, int n3,
             const float4* s4, uint2* d4, int n4,
             const float4* s5, uint2* d5, int n5,
             const float4* s6, uint2* d6, int n6)
{
    const float4* s; uint2* d; int n;
    switch (blockIdx.y) {
        case 0: s = s0; d = d0; n = n0; break;
        case 1: s = s1; d = d1; n = n1; break;
        case 2: s = s2; d = d2; n = n2; break;
        case 3: s = s3; d = d3; n = n3; break;
        case 4: s = s4; d = d4; n = n4; break;
        case 5: s = s5; d = d5; n = n5; break;
        default: s = s6; d = d6; n = n6; break;
    }
    int i = blockIdx.x*blockDim.x + threadIdx.x;
    if (i < n) {
        float4 v = s[i];
        uint2 o;
        o.x = f2h2(v.x, v.y);
        o.y = f2h2(v.z, v.w);
        d[i] = o;
    }
}

// ---------------------------------------------------------------------------
// GEMM core: BM=BN=128, BK=32, 256 thr (8 warps, 4m x 2n, warp tile 32x64),
// m16n8k16, 4-stage cp.async ring in dynamic smem (R10 config — best).
// ---------------------------------------------------------------------------
#define GPA 40
#define GPB 136
#define ABUF (128*GPA)            // halfs per A stage (5120)
#define BBUF (32*GPB)             // halfs per B stage (4352)
#define GSTAGES 4
#define GSMEM_BYTES (GSTAGES*(ABUF+BBUF)*2)   // 75776 B

#define GEMM_ISSUE(Aptr, Bptr, Kdim, Ndim, st, k0)                              \
    {                                                                           \
        const uint32_t oA = (uint32_t)((st)*ABUF*2);                            \
        const uint32_t oB = (uint32_t)((st)*BBUF*2);                            \
        cpa16(sAu + oA + dA0, (Aptr) + (size_t)ar0*(Kdim) + (k0) + ak0);        \
        cpa16(sAu + oA + dA1, (Aptr) + (size_t)ar1*(Kdim) + (k0) + ak1);        \
        cpa16(sBu + oB + dB0, (Bptr) + (size_t)((k0) + bk0)*(Ndim) + bn0);      \
        cpa16(sBu + oB + dB1, (Bptr) + (size_t)((k0) + bk1)*(Ndim) + bn0);      \
    }

#define GEMM_MAINLOOP(Aptr, Bptr, Kdim, Ndim)                                   \
    __half* smA = dsm;                                                          \
    __half* smB = dsm + GSTAGES*ABUF;                                           \
    const int ar0 = tid >> 2,         ak0 = (tid & 3) << 3;                     \
    const int ar1 = (tid + 256) >> 2, ak1 = ((tid + 256) & 3) << 3;             \
    const int bk0 = tid >> 4,         bn0 = (tid & 15) << 3;                    \
    const int bk1 = bk0 + 16;                                                   \
    const uint32_t sAu = smem_u32(smA);                                         \
    const uint32_t sBu = smem_u32(smB);                                         \
    const uint32_t dA0 = (uint32_t)((ar0*GPA + ak0) << 1);                      \
    const uint32_t dA1 = (uint32_t)((ar1*GPA + ak1) << 1);                      \
    const uint32_t dB0 = (uint32_t)((bk0*GPB + bn0) << 1);                      \
    const uint32_t dB1 = (uint32_t)((bk1*GPB + bn0) << 1);                      \
    uint32_t aAd[2], bAd[4];                                                    \
    _Pragma("unroll")                                                           \
    for (int mi = 0; mi < 2; mi++)                                              \
        aAd[mi] = sAu + (((wm*32 + mi*16 + (lane & 15))*GPA + (lane >> 4)*8) << 1); \
    _Pragma("unroll")                                                           \
    for (int nt = 0; nt < 4; nt++)                                              \
        bAd[nt] = sBu + ((((lane & 7) + ((lane >> 3) & 1)*8)*GPB                \
                          + wn*64 + nt*16 + (lane >> 4)*8) << 1);               \
    float acc[2][8][4];                                                         \
    _Pragma("unroll")                                                           \
    for (int mi = 0; mi < 2; mi++)                                              \
        _Pragma("unroll")                                                       \
        for (int ni = 0; ni < 8; ni++)                                          \
            _Pragma("unroll")                                                   \
            for (int c = 0; c < 4; c++) acc[mi][ni][c] = 0.f;                   \
    const int KT = (Kdim) >> 5;                                                 \
    GEMM_ISSUE(Aptr, Bptr, Kdim, Ndim, 0, 0)  cpa_commit();                     \
    GEMM_ISSUE(Aptr, Bptr, Kdim, Ndim, 1, 32) cpa_commit();                     \
    GEMM_ISSUE(Aptr, Bptr, Kdim, Ndim, 2, 64) cpa_commit();                     \
    for (int kt = 0; kt < KT; kt++) {                                           \
        const int st = kt & (GSTAGES - 1);                                      \
        cpa_wait<GSTAGES - 2>();                                                \
        __syncthreads();                                                        \
        if (kt + 3 < KT) {                                                      \
            const int ns = (kt + 3) & (GSTAGES - 1);                            \
            GEMM_ISSUE(Aptr, Bptr, Kdim, Ndim, ns, (kt + 3)*32)                 \
        }                                                                       \
        cpa_commit();                                                           \
        const uint32_t boA = (uint32_t)(st*ABUF*2);                             \
        const uint32_t boB = (uint32_t)(st*BBUF*2);                             \
        _Pragma("unroll")                                                       \
        for (int kh = 0; kh < 2; kh++) {                                        \
            uint32_t af[2][4], bf[4][4];                                        \
            ldsm4(af[0], aAd[0] + boA + kh*32);                                 \
            ldsm4(af[1], aAd[1] + boA + kh*32);                                 \
            _Pragma("unroll")                                                   \
            for (int nt = 0; nt < 4; nt++)                                      \
                ldsm4t(bf[nt], bAd[nt] + boB + kh*16*GPB*2);                    \
            _Pragma("unroll")                                                   \
            for (int nt = 0; nt < 4; nt++) {                                    \
                _Pragma("unroll")                                               \
                for (int mi = 0; mi < 2; mi++) {                                \
                    mma_f16(acc[mi][2*nt],   af[mi], bf[nt][0], bf[nt][1]);     \
                    mma_f16(acc[mi][2*nt+1], af[mi], bf[nt][2], bf[nt][3]);     \
                }                                                               \
            }                                                                   \
        }                                                                       \
    }

// ---------------------------------------------------------------------------
// General fp16 GEMM with fused epilogues.
//  EPI 1: half out, bias+relu   EPI 2: f32 out, bias+residual
// ---------------------------------------------------------------------------
template<int EPI>
__global__ __launch_bounds__(256, 2)
void gemm_h(const __half* __restrict__ A, const __half* __restrict__ B,
            const float* __restrict__ bias, const float* __restrict__ res,
            void* __restrict__ Cv, int M, int N, int K)
{
    extern __shared__ __half dsm[];

    const int tid = threadIdx.x;
    const int lane = tid & 31, wid = tid >> 5;
    const int wm = wid & 3, wn = wid >> 2;
    const int bx = blockIdx.x, by = blockIdx.y;

    const __half* Ag = A + (size_t)(by*128)*K;
    const __half* Bg = B + (size_t)bx*128;

    GEMM_MAINLOOP(Ag, Bg, K, N)

    const int r0 = (by*128) + wm*32 + (lane >> 2);
#pragma unroll
    for (int mi = 0; mi < 2; mi++) {
        const int gr = r0 + mi*16;
#pragma unroll
        for (int ni = 0; ni < 8; ni++) {
            const int gc = (bx*128) + wn*64 + (ni >> 1)*16 + (ni & 1)*8
                         + ((lane & 3) << 1);
            const float2 bia = *(const float2*)(bias + gc);
            float2 v0 = make_float2(acc[mi][ni][0] + bia.x, acc[mi][ni][1] + bia.y);
            float2 v1 = make_float2(acc[mi][ni][2] + bia.x, acc[mi][ni][3] + bia.y);
            if (EPI == 1) {
                v0.x = fmaxf(v0.x, 0.f); v0.y = fmaxf(v0.y, 0.f);
                v1.x = fmaxf(v1.x, 0.f); v1.y = fmaxf(v1.y, 0.f);
                __half* Ch = (__half*)Cv;
                *(__half2*)(Ch + (size_t)gr*N + gc)     = __floats2half2_rn(v0.x, v0.y);
                *(__half2*)(Ch + (size_t)(gr+8)*N + gc) = __floats2half2_rn(v1.x, v1.y);
            } else {  // EPI == 2
                const float2 r_0 = *(const float2*)(res + (size_t)gr*N + gc);
                const float2 r_1 = *(const float2*)(res + (size_t)(gr+8)*N + gc);
                v0.x += r_0.x; v0.y += r_0.y;
                v1.x += r_1.x; v1.y += r_1.y;
                float* Cf = (float*)Cv;
                *(float2*)(Cf + (size_t)gr*N + gc)     = v0;
                *(float2*)(Cf + (size_t)(gr+8)*N + gc) = v1;
            }
        }
    }
}

// ---------------------------------------------------------------------------
// Fused QKV projection: grid (12, 64). bx>>2 selects Q/K/V.
// ---------------------------------------------------------------------------
__global__ __launch_bounds__(256, 2)
void gemm_qkv(const __half* __restrict__ A,
              const __half* __restrict__ Bq, const __half* __restrict__ Bk,
              const __half* __restrict__ Bv,
              const float* __restrict__ bq, const float* __restrict__ bk,
              const float* __restrict__ bv,
              __half* __restrict__ Oq, __half* __restrict__ Ok,
              __half* __restrict__ Ovt)
{
    extern __shared__ __half dsm[];

    const int tid = threadIdx.x;
    const int lane = tid & 31, wid = tid >> 5;
    const int wm = wid & 3, wn = wid >> 2;
    const int sel = blockIdx.x >> 2, bx = blockIdx.x & 3;
    const int by = blockIdx.y;
    const int N = DM, K = DM;

    const __half* B  = (sel == 0) ? Bq : (sel == 1) ? Bk : Bv;
    const float* bia_p = (sel == 0) ? bq : (sel == 1) ? bk : bv;

    const __half* Ag = A + (size_t)(by*128)*K;
    const __half* Bg = B + (size_t)bx*128;

    GEMM_MAINLOOP(Ag, Bg, K, N)

    const int r0 = (by*128) + wm*32 + (lane >> 2);
#pragma unroll
    for (int mi = 0; mi < 2; mi++) {
        const int gr = r0 + mi*16;
#pragma unroll
        for (int ni = 0; ni < 8; ni++) {
            const int gc = (bx*128) + wn*64 + (ni >> 1)*16 + (ni & 1)*8
                         + ((lane & 3) << 1);
            const float2 bia = *(const float2*)(bia_p + gc);
            float2 v0 = make_float2(acc[mi][ni][0] + bia.x, acc[mi][ni][1] + bia.y);
            float2 v1 = make_float2(acc[mi][ni][2] + bia.x, acc[mi][ni][3] + bia.y);
            if (sel == 0) {
                *(__half2*)(Oq + (size_t)gr*N + gc) =
                    __floats2half2_rn(v0.x*0.125f, v0.y*0.125f);
                *(__half2*)(Oq + (size_t)(gr+8)*N + gc) =
                    __floats2half2_rn(v1.x*0.125f, v1.y*0.125f);
            } else if (sel == 1) {
                *(__half2*)(Ok + (size_t)gr*N + gc)     = __floats2half2_rn(v0.x, v0.y);
                *(__half2*)(Ok + (size_t)(gr+8)*N + gc) = __floats2half2_rn(v1.x, v1.y);
            } else {
                Ovt[(size_t)gc*ROWS + gr]         = __float2half_rn(v0.x);
                Ovt[(size_t)(gc+1)*ROWS + gr]     = __float2half_rn(v0.y);
                Ovt[(size_t)gc*ROWS + gr + 8]     = __float2half_rn(v1.x);
                Ovt[(size_t)(gc+1)*ROWS + gr + 8] = __float2half_rn(v1.y);
            }
        }
    }
}

// ---------------------------------------------------------------------------
// FP16 flash attention, 64 q-rows / 128 threads / 4 warps per CTA,
// 2 CTAs per SM. Softmax exp via ex2.approx.f16x2 (h2exp2).
// ---------------------------------------------------------------------------
#define AT_PA 136
#define AT_PK 72
#define AT_AH (64*AT_PA)
#define AT_KH (128*AT_PK)
#define AT_VH (64*AT_PA)
#define AT_OFF_K AT_AH
#define AT_OFF_V (AT_OFF_K + 2*AT_KH)
#define AT_SMEM_BYTES ((AT_OFF_V + 2*AT_VH)*2)   // 89088 B
#define LOG2E 1.44269504f

__global__ __launch_bounds__(128, 2)
void attn_f16(const __half* __restrict__ Qh, const __half* __restrict__ Kh,
              const __half* __restrict__ Vth, __half* __restrict__ Oh)
{
    extern __shared__ __half smh[];
    __half* sA = smh;

    const int n = blockIdx.z, h = blockIdx.y;
    const int tid = threadIdx.x, lane = tid & 31, w = tid >> 5;
    const size_t base  = ((size_t)n*SEQ)*DM + h*EHEAD;
    const size_t vbase = ((size_t)h*EHEAD)*ROWS + (size_t)n*SEQ;
    const int q0 = blockIdx.x * 64;

    const uint32_t sAu = smem_u32(sA);
    const uint32_t sKu = smem_u32(smh + AT_OFF_K);
    const uint32_t sVu = smem_u32(smh + AT_OFF_V);

#pragma unroll
    for (int j = 0; j < 4; j++) {
        int idx = j*128 + tid;
        int r = idx >> 3, c8 = (idx & 7) << 3;
        cpa16(sAu + (uint32_t)((r*AT_PA + c8) << 1),
              Qh + base + (size_t)(q0 + r)*DM + c8);
    }
    cpa_commit();
#pragma unroll
    for (int j = 0; j < 8; j++) {
        int idx = j*128 + tid;
        int r = idx >> 3, c8 = (idx & 7) << 3;
        cpa16(sKu + (uint32_t)((r*AT_PK + c8) << 1),
              Kh + base + (size_t)r*DM + c8);
    }
#pragma unroll
    for (int j = 0; j < 8; j++) {
        int idx = j*128 + tid;
        int r = idx >> 4, c8 = (idx & 15) << 3;
        cpa16(sVu + (uint32_t)((r*AT_PA + c8) << 1),
              Vth + vbase + (size_t)r*ROWS + c8);
    }
    cpa_commit();

    cpa_wait<1>();
    __syncthreads();

    const uint32_t aBase = sAu + (((w*16 + (lane & 15))*AT_PA + (lane >> 4)*8) << 1);
    uint32_t aQ[4][4];
#pragma unroll
    for (int ks = 0; ks < 4; ks++) ldsm4(aQ[ks], aBase + ks*32);

    uint32_t bK[8], bV[4];
#pragma unroll
    for (int p = 0; p < 8; p++)
        bK[p] = sKu + (((p*16 + (lane & 7) + ((lane >> 3) & 1)*8)*AT_PK
                        + (lane >> 4)*8) << 1);
#pragma unroll
    for (int p = 0; p < 4; p++)
        bV[p] = sVu + (((p*16 + (lane & 7) + ((lane >> 3) & 1)*8)*AT_PA
                        + (lane >> 4)*8) << 1);

    float accO[8][4];
#pragma unroll
    for (int ni = 0; ni < 8; ni++)
#pragma unroll
        for (int c = 0; c < 4; c++) accO[ni][c] = 0.f;
    float m0 = -1e30f, m1 = -1e30f, l0 = 0.f, l1 = 0.f;

    const int rA = w*16 + (lane >> 2);
    __half* pr0 = &sA[rA*AT_PA + 2*(lane & 3)];
    __half* pr1 = pr0 + 8*AT_PA;

    for (int kt = 0; kt < SEQ/128; kt++) {
        const int buf = kt & 1;
        if (kt + 1 < SEQ/128) {
            const int nb = buf ^ 1;
            const uint32_t ko = (uint32_t)(nb * AT_KH) << 1;
            const uint32_t vo = (uint32_t)(nb * AT_VH) << 1;
#pragma unroll
            for (int j = 0; j < 8; j++) {
                int idx = j*128 + tid;
                int r = idx >> 3, c8 = (idx & 7) << 3;
                cpa16(sKu + ko + (uint32_t)((r*AT_PK + c8) << 1),
                      Kh + base + (size_t)((kt+1)*128 + r)*DM + c8);
            }
#pragma unroll
            for (int j = 0; j < 8; j++) {
                int idx = j*128 + tid;
                int r = idx >> 4, c8 = (idx & 15) << 3;
                cpa16(sVu + vo + (uint32_t)((r*AT_PA + c8) << 1),
                      Vth + vbase + (size_t)r*ROWS + (kt+1)*128 + c8);
            }
            cpa_commit();
            cpa_wait<1>();
        } else {
            cpa_wait<0>();
        }
        __syncthreads();

        const uint32_t ko = (uint32_t)(buf * AT_KH) << 1;
        const uint32_t vo = (uint32_t)(buf * AT_VH) << 1;

        // ---- S = Q K^T ----
        float accS[16][4];
#pragma unroll
        for (int t = 0; t < 16; t++)
#pragma unroll
            for (int c = 0; c < 4; c++) accS[t][c] = 0.f;
#pragma unroll
        for (int ks = 0; ks < 4; ks++) {
#pragma unroll
            for (int p = 0; p < 8; p++) {
                uint32_t bf[4];
                ldsm4(bf, bK[p] + ko + ks*32);
                mma_f16(accS[2*p],   aQ[ks], bf[0], bf[2]);
                mma_f16(accS[2*p+1], aQ[ks], bf[1], bf[3]);
            }
        }

        // ---- online softmax (fp32 stats, fp16x2 exp) ----
        float rmax0 = -1e30f, rmax1 = -1e30f;
#pragma unroll
        for (int t = 0; t < 16; t++) {
            rmax0 = fmaxf(rmax0, fmaxf(accS[t][0], accS[t][1]));
            rmax1 = fmaxf(rmax1, fmaxf(accS[t][2], accS[t][3]));
        }
        rmax0 = fmaxf(rmax0, __shfl_xor_sync(0xffffffffu, rmax0, 1));
        rmax0 = fmaxf(rmax0, __shfl_xor_sync(0xffffffffu, rmax0, 2));
        rmax1 = fmaxf(rmax1, __shfl_xor_sync(0xffffffffu, rmax1, 1));
        rmax1 = fmaxf(rmax1, __shfl_xor_sync(0xffffffffu, rmax1, 2));
        const float mn0 = fmaxf(m0, rmax0), mn1 = fmaxf(m1, rmax1);
        const float cr0 = __expf(m0 - mn0), cr1 = __expf(m1 - mn1);
        m0 = mn0; m1 = mn1;
        l0 *= cr0; l1 *= cr1;
#pragma unroll
        for (int ni = 0; ni < 8; ni++) {
            accO[ni][0] *= cr0; accO[ni][1] *= cr0;
            accO[ni][2] *= cr1; accO[ni][3] *= cr1;
        }
#pragma unroll
        for (int t = 0; t < 16; t++) {
            // p = 2^((s-m)*log2e), computed pairwise in fp16
            __half2 a0 = __floats2half2_rn((accS[t][0] - m0)*LOG2E,
                                           (accS[t][1] - m0)*LOG2E);
            __half2 a1 = __floats2half2_rn((accS[t][2] - m1)*LOG2E,
                                           (accS[t][3] - m1)*LOG2E);
            __half2 p0 = h2exp2(a0);
            __half2 p1 = h2exp2(a1);
            *(__half2*)(pr0 + t*8) = p0;
            *(__half2*)(pr1 + t*8) = p1;
            float2 f0 = __half22float2(p0);
            float2 f1 = __half22float2(p1);
            l0 += f0.x + f0.y;
            l1 += f1.x + f1.y;
        }
        __syncwarp();

        // ---- O += P V ----
#pragma unroll
        for (int ks = 0; ks < 8; ks++) {
            uint32_t aP[4];
            ldsm4(aP, aBase + ks*32);
#pragma unroll
            for (int p = 0; p < 4; p++) {
                uint32_t bf[4];
                ldsm4(bf, bV[p] + vo + ks*32);
                mma_f16(accO[2*p],   aP, bf[0], bf[2]);
                mma_f16(accO[2*p+1], aP, bf[1], bf[3]);
            }
        }
        __syncthreads();
    }

    l0 += __shfl_xor_sync(0xffffffffu, l0, 1);
    l0 += __shfl_xor_sync(0xffffffffu, l0, 2);
    l1 += __shfl_xor_sync(0xffffffffu, l1, 1);
    l1 += __shfl_xor_sync(0xffffffffu, l1, 2);
    const float inv0 = 1.f / l0, inv1 = 1.f / l1;
    const int gr0 = q0 + w*16 + (lane >> 2);
    const int cc = 2*(lane & 3);
#pragma unroll
    for (int ni = 0; ni < 8; ni++) {
        *(__half2*)(Oh + base + (size_t)gr0*DM + ni*8 + cc) =
            __floats2half2_rn(accO[ni][0]*inv0, accO[ni][1]*inv0);
        *(__half2*)(Oh + base + (size_t)(gr0+8)*DM + ni*8 + cc) =
            __floats2half2_rn(accO[ni][2]*inv1, accO[ni][3]*inv1);
    }
}

// ---------------------------------------------------------------------------
// LayerNorm (512): one WARP per row, 256 threads = 8 rows/CTA, shfl-only.
// ---------------------------------------------------------------------------
__global__ __launch_bounds__(256)
void ln_kernel(const float* __restrict__ in, const float* __restrict__ gamma,
               const float* __restrict__ beta, float* __restrict__ out,
               __half* __restrict__ out16)
{
    const int w = threadIdx.x >> 5, lane = threadIdx.x & 31;
    const int row = blockIdx.x*8 + w;
    const float4* p = (const float4*)(in + (size_t)row*DM);

    float4 v[4];
    float s = 0.f, sq = 0.f;
#pragma unroll
    for (int i = 0; i < 4; i++) {
        v[i] = p[lane + 32*i];
        s  += v[i].x + v[i].y + v[i].z + v[i].w;
        sq += v[i].x*v[i].x + v[i].y*v[i].y + v[i].z*v[i].z + v[i].w*v[i].w;
    }
#pragma unroll
    for (int o = 16; o; o >>= 1) {
        s  += __shfl_xor_sync(0xffffffffu, s,  o);
        sq += __shfl_xor_sync(0xffffffffu, sq, o);
    }
    const float mean = s * (1.f / DM);
    const float var  = sq * (1.f / DM) - mean * mean;
    const float inv  = rsqrtf(var + LN_EPS);

    float4* op = (float4*)(out + (size_t)row*DM);
    uint2*  hp = out16 ? (uint2*)(out16 + (size_t)row*DM) : nullptr;
#pragma unroll
    for (int i = 0; i < 4; i++) {
        const float4 g4 = ((const float4*)gamma)[lane + 32*i];
        const float4 b4 = ((const float4*)beta)[lane + 32*i];
        float4 o4;
        o4.x = (v[i].x - mean)*inv*g4.x + b4.x;
        o4.y = (v[i].y - mean)*inv*g4.y + b4.y;
        o4.z = (v[i].z - mean)*inv*g4.z + b4.z;
        o4.w = (v[i].w - mean)*inv*g4.w + b4.w;
        op[lane + 32*i] = o4;
        if (hp) {
            uint2 h;
            h.x = f2h2(o4.x, o4.y);
            h.y = f2h2(o4.z, o4.w);
            hp[lane + 32*i] = h;
        }
    }
}

// ---------------------------------------------------------------------------
extern "C" void kernel_launch(void* const* d_in, const int* in_sizes, int n_in,
                              void* d_out, int out_size)
{
    const float* x   = (const float*)d_in[0];
    const float* Wq  = (const float*)d_in[1];
    const float* bq  = (const float*)d_in[2];
    const float* Wk  = (const float*)d_in[3];
    const float* bk  = (const float*)d_in[4];
    const float* Wv  = (const float*)d_in[5];
    const float* bv  = (const float*)d_in[6];
    const float* Wo  = (const float*)d_in[7];
    const float* bo  = (const float*)d_in[8];
    const float* W1  = (const float*)d_in[9];
    const float* b1  = (const float*)d_in[10];
    const float* W2  = (const float*)d_in[11];
    const float* b2  = (const float*)d_in[12];
    const float* g1  = (const float*)d_in[13];
    const float* be1 = (const float*)d_in[14];
    const float* g2  = (const float*)d_in[15];
    const float* be2 = (const float*)d_in[16];

    __half *qh, *kh, *vth, *oh, *xh, *h1h, *ffh;
    __half *wqh, *wkh, *wvh, *woh, *w1h, *w2h;
    float *hb, *h1, *h2, *xb;
    cudaGetSymbolAddress((void**)&qh,  g_qh);
    cudaGetSymbolAddress((void**)&kh,  g_kh);
    cudaGetSymbolAddress((void**)&vth, g_vth);
    cudaGetSymbolAddress((void**)&oh,  g_oh);
    cudaGetSymbolAddress((void**)&xh,  g_xh);
    cudaGetSymbolAddress((void**)&h1h, g_h1h);
    cudaGetSymbolAddress((void**)&ffh, g_ffh);
    cudaGetSymbolAddress((void**)&hb,  g_h);
    cudaGetSymbolAddress((void**)&h1,  g_h1);
    cudaGetSymbolAddress((void**)&h2,  g_h2);
    cudaGetSymbolAddress((void**)&xb,  g_x);
    cudaGetSymbolAddress((void**)&wqh, g_wq);
    cudaGetSymbolAddress((void**)&wkh, g_wk);
    cudaGetSymbolAddress((void**)&wvh, g_wv);
    cudaGetSymbolAddress((void**)&woh, g_wo);
    cudaGetSymbolAddress((void**)&w1h, g_w1);
    cudaGetSymbolAddress((void**)&w2h, g_w2);

    cudaFuncSetAttribute(attn_f16, cudaFuncAttributeMaxDynamicSharedMemorySize,
                         AT_SMEM_BYTES);
    cudaFuncSetAttribute(gemm_h<1>, cudaFuncAttributeMaxDynamicSharedMemorySize,
                         GSMEM_BYTES);
    cudaFuncSetAttribute(gemm_h<2>, cudaFuncAttributeMaxDynamicSharedMemorySize,
                         GSMEM_BYTES);
    cudaFuncSetAttribute(gemm_qkv, cudaFuncAttributeMaxDynamicSharedMemorySize,
                         GSMEM_BYTES);

    // ---- one launch: fp32 -> fp16 for 6 weight arrays + layer-0 input ----
    {
        const int nqkv = NLAYERS*DM*DM/4;
        const int nff  = NLAYERS*DM*DFF/4;
        const int nx   = ROWS*DM/4;
        const int maxb = (nff + 255) / 256;
        dim3 g(maxb, 7);
        f2h_all<<<g, 256>>>((const float4*)Wq, (uint2*)wqh, nqkv,
                            (const float4*)Wk, (uint2*)wkh, nqkv,
                            (const float4*)Wv, (uint2*)wvh, nqkv,
                            (const float4*)Wo, (uint2*)woh, nqkv,
                            (const float4*)W1, (uint2*)w1h, nff,
                            (const float4*)W2, (uint2*)w2h, nff,
                            (const float4*)x,  (uint2*)xh,  nx);
    }

    const dim3 gQKV(12, ROWS / 128);           // (12, 64) fused QKV
    const dim3 gProj(DM / 128, ROWS / 128);    // (4, 64)
    const dim3 gFF1 (DFF / 128, ROWS / 128);   // (16, 64)
    const dim3 gAttn(SEQ / 64, NHEAD, NB);     // (16, 8, 8)
    const dim3 gLN(ROWS / 8);                  // 1024 blocks, warp-per-row

    const float* hin = x;
    for (int l = 0; l < NLAYERS; l++) {
        const __half* wq = wqh + (size_t)l*DM*DM;
        const __half* wk = wkh + (size_t)l*DM*DM;
        const __half* wv = wvh + (size_t)l*DM*DM;
        const __half* wo = woh + (size_t)l*DM*DM;
        const __half* w1 = w1h + (size_t)l*DM*DFF;
        const __half* w2 = w2h + (size_t)l*DFF*DM;

        gemm_qkv<<<gQKV, 256, GSMEM_BYTES>>>(xh, wq, wk, wv,
                                             bq + l*DM, bk + l*DM, bv + l*DM,
                                             qh, kh, vth);

        attn_f16<<<gAttn, 128, AT_SMEM_BYTES>>>(qh, kh, vth, oh);

        gemm_h<2><<<gProj, 256, GSMEM_BYTES>>>(oh, wo, bo + l*DM, hin, hb,
                                               ROWS, DM, DM);
        ln_kernel<<<gLN, 256>>>(hb, g1 + l*DM, be1 + l*DM, h1, h1h);

        gemm_h<1><<<gFF1, 256, GSMEM_BYTES>>>(h1h, w1, b1 + l*DFF, nullptr, ffh,
                                              ROWS, DFF, DM);
        gemm_h<2><<<gProj, 256, GSMEM_BYTES>>>(ffh, w2, b2 + l*DM, h1, h2,
                                               ROWS, DM, DFF);

        float* lnout = (l == NLAYERS - 1) ? (float*)d_out : xb;
        __half* lnout16 = (l == NLAYERS - 1) ? (__half*)nullptr : xh;
        ln_kernel<<<gLN, 256>>>(h2, g2 + l*DM, be2 + l*DM, lnout, lnout16);
        hin = xb;
    }
}

// round 14
// speedup vs baseline: 1.0811x; 1.0133x over previous
#include <cuda_runtime.h>
#include <cuda_fp16.h>
#include <cstdint>
#include <cstddef>

// Problem constants
#define DM      512
#define DFF     2048
#define NB      8
#define SEQ     1024
#define NHEAD   8
#define EHEAD   64
#define ROWS    (NB*SEQ)     // 8192
#define NLAYERS 4
#define LN_EPS  1e-5f

// ---------------- scratch (device globals; no allocations allowed) --------
__device__ __half g_qh [ROWS*DM];    // Q (pre-scaled 1/8)
__device__ __half g_kh [ROWS*DM];
__device__ __half g_vth[DM*ROWS];    // V^T [col][token]
__device__ __half g_oh [ROWS*DM];    // attention out
__device__ __half g_xh [ROWS*DM];    // fp16 copy of layer input
__device__ __half g_h1h[ROWS*DM];    // fp16 copy of post-LN1
__device__ __half g_ffh[ROWS*DFF];   // ReLU(FFN1) in fp16
__device__ float  g_h  [ROWS*DM];
__device__ float  g_h1 [ROWS*DM];
__device__ float  g_h2 [ROWS*DM];
__device__ float  g_x  [ROWS*DM];
// fp16 weights (converted once per launch)
__device__ __half g_wq[NLAYERS*DM*DM];
__device__ __half g_wk[NLAYERS*DM*DM];
__device__ __half g_wv[NLAYERS*DM*DM];
__device__ __half g_wo[NLAYERS*DM*DM];
__device__ __half g_w1[NLAYERS*DM*DFF];
__device__ __half g_w2[NLAYERS*DFF*DM];

// ---------------- helpers ---------------------------------------------------
__device__ __forceinline__ uint32_t f2h2(float a, float b) {
    __half2 h = __floats2half2_rn(a, b);
    return *(uint32_t*)&h;
}
__device__ __forceinline__ void ldsm4(uint32_t* r, uint32_t addr) {
    asm volatile("ldmatrix.sync.aligned.m8n8.x4.shared.b16 {%0,%1,%2,%3}, [%4];\n"
                 : "=r"(r[0]), "=r"(r[1]), "=r"(r[2]), "=r"(r[3]) : "r"(addr));
}
__device__ __forceinline__ void ldsm4t(uint32_t* r, uint32_t addr) {
    asm volatile("ldmatrix.sync.aligned.m8n8.x4.trans.shared.b16 {%0,%1,%2,%3}, [%4];\n"
                 : "=r"(r[0]), "=r"(r[1]), "=r"(r[2]), "=r"(r[3]) : "r"(addr));
}
__device__ __forceinline__ void mma_f16(float* d, const uint32_t* a,
                                        uint32_t b0, uint32_t b1) {
    asm volatile(
        "mma.sync.aligned.m16n8k16.row.col.f32.f16.f16.f32 "
        "{%0,%1,%2,%3},{%4,%5,%6,%7},{%8,%9},{%0,%1,%2,%3};\n"
        : "+f"(d[0]), "+f"(d[1]), "+f"(d[2]), "+f"(d[3])
        : "r"(a[0]), "r"(a[1]), "r"(a[2]), "r"(a[3]), "r"(b0), "r"(b1));
}
__device__ __forceinline__ uint32_t smem_u32(const void* p) {
    return (uint32_t)__cvta_generic_to_shared(p);
}
// cp.async with L1 bypass (cg): fills have zero reuse, keep them out of L1tex
__device__ __forceinline__ void cpa16(uint32_t dst, const void* src) {
    asm volatile("cp.async.cg.shared.global [%0], [%1], 16;\n"
                 :: "r"(dst), "l"(src) : "memory");
}
__device__ __forceinline__ void cpa_commit() {
    asm volatile("cp.async.commit_group;\n" ::: "memory");
}
template<int N>
__device__ __forceinline__ void cpa_wait() {
    asm volatile("cp.async.wait_group %0;\n" :: "n"(N) : "memory");
}

// ---------------- fp32 -> fp16 bulk convert (all 7 arrays, one launch) -----
__global__ __launch_bounds__(256)
void f2h_all(const float4* s0, uint2* d0, int n0,
             const float4* s1, uint2* d1, int n1,
             const float4* s2, uint2* d2, int n2,
             const float4* s3, uint2* d3, int n3,
             const float4* s4, uint2* d4, int n4,
             const float4* s5, uint2* d5, int n5,
             const float4* s6, uint2* d6, int n6)
{
    const float4* s; uint2* d; int n;
    switch (blockIdx.y) {
        case 0: s = s0; d = d0; n = n0; break;
        case 1: s = s1; d = d1; n = n1; break;
        case 2: s = s2; d = d2; n = n2; break;
        case 3: s = s3; d = d3; n = n3; break;
        case 4: s = s4; d = d4; n = n4; break;
        case 5: s = s5; d = d5; n = n5; break;
        default: s = s6; d = d6; n = n6; break;
    }
    int i = blockIdx.x*blockDim.x + threadIdx.x;
    if (i < n) {
        float4 v = s[i];
        uint2 o;
        o.x = f2h2(v.x, v.y);
        o.y = f2h2(v.z, v.w);
        d[i] = o;
    }
}

// ---------------------------------------------------------------------------
// GEMM core: BM=BN=128, BK=32, 256 thr (8 warps, 4m x 2n, warp tile 32x64),
// m16n8k16, 4-stage cp.async ring in dynamic smem (R10 config — best).
// ---------------------------------------------------------------------------
#define GPA 40
#define GPB 136
#define ABUF (128*GPA)            // halfs per A stage (5120)
#define BBUF (32*GPB)             // halfs per B stage (4352)
#define GSTAGES 4
#define GSMEM_BYTES (GSTAGES*(ABUF+BBUF)*2)   // 75776 B

#define GEMM_ISSUE(Aptr, Bptr, Kdim, Ndim, st, k0)                              \
    {                                                                           \
        const uint32_t oA = (uint32_t)((st)*ABUF*2);                            \
        const uint32_t oB = (uint32_t)((st)*BBUF*2);                            \
        cpa16(sAu + oA + dA0, (Aptr) + (size_t)ar0*(Kdim) + (k0) + ak0);        \
        cpa16(sAu + oA + dA1, (Aptr) + (size_t)ar1*(Kdim) + (k0) + ak1);        \
        cpa16(sBu + oB + dB0, (Bptr) + (size_t)((k0) + bk0)*(Ndim) + bn0);      \
        cpa16(sBu + oB + dB1, (Bptr) + (size_t)((k0) + bk1)*(Ndim) + bn0);      \
    }

#define GEMM_MAINLOOP(Aptr, Bptr, Kdim, Ndim)                                   \
    __half* smA = dsm;                                                          \
    __half* smB = dsm + GSTAGES*ABUF;                                           \
    const int ar0 = tid >> 2,         ak0 = (tid & 3) << 3;                     \
    const int ar1 = (tid + 256) >> 2, ak1 = ((tid + 256) & 3) << 3;             \
    const int bk0 = tid >> 4,         bn0 = (tid & 15) << 3;                    \
    const int bk1 = bk0 + 16;                                                   \
    const uint32_t sAu = smem_u32(smA);                                         \
    const uint32_t sBu = smem_u32(smB);                                         \
    const uint32_t dA0 = (uint32_t)((ar0*GPA + ak0) << 1);                      \
    const uint32_t dA1 = (uint32_t)((ar1*GPA + ak1) << 1);                      \
    const uint32_t dB0 = (uint32_t)((bk0*GPB + bn0) << 1);                      \
    const uint32_t dB1 = (uint32_t)((bk1*GPB + bn0) << 1);                      \
    uint32_t aAd[2], bAd[4];                                                    \
    _Pragma("unroll")                                                           \
    for (int mi = 0; mi < 2; mi++)                                              \
        aAd[mi] = sAu + (((wm*32 + mi*16 + (lane & 15))*GPA + (lane >> 4)*8) << 1); \
    _Pragma("unroll")                                                           \
    for (int nt = 0; nt < 4; nt++)                                              \
        bAd[nt] = sBu + ((((lane & 7) + ((lane >> 3) & 1)*8)*GPB                \
                          + wn*64 + nt*16 + (lane >> 4)*8) << 1);               \
    float acc[2][8][4];                                                         \
    _Pragma("unroll")                                                           \
    for (int mi = 0; mi < 2; mi++)                                              \
        _Pragma("unroll")                                                       \
        for (int ni = 0; ni < 8; ni++)                                          \
            _Pragma("unroll")                                                   \
            for (int c = 0; c < 4; c++) acc[mi][ni][c] = 0.f;                   \
    const int KT = (Kdim) >> 5;                                                 \
    GEMM_ISSUE(Aptr, Bptr, Kdim, Ndim, 0, 0)  cpa_commit();                     \
    GEMM_ISSUE(Aptr, Bptr, Kdim, Ndim, 1, 32) cpa_commit();                     \
    GEMM_ISSUE(Aptr, Bptr, Kdim, Ndim, 2, 64) cpa_commit();                     \
    for (int kt = 0; kt < KT; kt++) {                                           \
        const int st = kt & (GSTAGES - 1);                                      \
        cpa_wait<GSTAGES - 2>();                                                \
        __syncthreads();                                                        \
        if (kt + 3 < KT) {                                                      \
            const int ns = (kt + 3) & (GSTAGES - 1);                            \
            GEMM_ISSUE(Aptr, Bptr, Kdim, Ndim, ns, (kt + 3)*32)                 \
        }                                                                       \
        cpa_commit();                                                           \
        const uint32_t boA = (uint32_t)(st*ABUF*2);                             \
        const uint32_t boB = (uint32_t)(st*BBUF*2);                             \
        _Pragma("unroll")                                                       \
        for (int kh = 0; kh < 2; kh++) {                                        \
            uint32_t af[2][4], bf[4][4];                                        \
            ldsm4(af[0], aAd[0] + boA + kh*32);                                 \
            ldsm4(af[1], aAd[1] + boA + kh*32);                                 \
            _Pragma("unroll")                                                   \
            for (int nt = 0; nt < 4; nt++)                                      \
                ldsm4t(bf[nt], bAd[nt] + boB + kh*16*GPB*2);                    \
            _Pragma("unroll")                                                   \
            for (int nt = 0; nt < 4; nt++) {                                    \
                _Pragma("unroll")                                               \
                for (int mi = 0; mi < 2; mi++) {                                \
                    mma_f16(acc[mi][2*nt],   af[mi], bf[nt][0], bf[nt][1]);     \
                    mma_f16(acc[mi][2*nt+1], af[mi], bf[nt][2], bf[nt][3]);     \
                }                                                               \
            }                                                                   \
        }                                                                       \
    }

// ---------------------------------------------------------------------------
// General fp16 GEMM with fused epilogues.
//  EPI 1: half out, bias+relu   EPI 2: f32 out, bias+residual
// ---------------------------------------------------------------------------
template<int EPI>
__global__ __launch_bounds__(256, 2)
void gemm_h(const __half* __restrict__ A, const __half* __restrict__ B,
            const float* __restrict__ bias, const float* __restrict__ res,
            void* __restrict__ Cv, int M, int N, int K)
{
    extern __shared__ __half dsm[];

    const int tid = threadIdx.x;
    const int lane = tid & 31, wid = tid >> 5;
    const int wm = wid & 3, wn = wid >> 2;
    const int bx = blockIdx.x, by = blockIdx.y;

    const __half* Ag = A + (size_t)(by*128)*K;
    const __half* Bg = B + (size_t)bx*128;

    GEMM_MAINLOOP(Ag, Bg, K, N)

    const int r0 = (by*128) + wm*32 + (lane >> 2);
#pragma unroll
    for (int mi = 0; mi < 2; mi++) {
        const int gr = r0 + mi*16;
#pragma unroll
        for (int ni = 0; ni < 8; ni++) {
            const int gc = (bx*128) + wn*64 + (ni >> 1)*16 + (ni & 1)*8
                         + ((lane & 3) << 1);
            const float2 bia = *(const float2*)(bias + gc);
            float2 v0 = make_float2(acc[mi][ni][0] + bia.x, acc[mi][ni][1] + bia.y);
            float2 v1 = make_float2(acc[mi][ni][2] + bia.x, acc[mi][ni][3] + bia.y);
            if (EPI == 1) {
                v0.x = fmaxf(v0.x, 0.f); v0.y = fmaxf(v0.y, 0.f);
                v1.x = fmaxf(v1.x, 0.f); v1.y = fmaxf(v1.y, 0.f);
                __half* Ch = (__half*)Cv;
                *(__half2*)(Ch + (size_t)gr*N + gc)     = __floats2half2_rn(v0.x, v0.y);
                *(__half2*)(Ch + (size_t)(gr+8)*N + gc) = __floats2half2_rn(v1.x, v1.y);
            } else {  // EPI == 2
                const float2 r_0 = *(const float2*)(res + (size_t)gr*N + gc);
                const float2 r_1 = *(const float2*)(res + (size_t)(gr+8)*N + gc);
                v0.x += r_0.x; v0.y += r_0.y;
                v1.x += r_1.x; v1.y += r_1.y;
                float* Cf = (float*)Cv;
                *(float2*)(Cf + (size_t)gr*N + gc)     = v0;
                *(float2*)(Cf + (size_t)(gr+8)*N + gc) = v1;
            }
        }
    }
}

// ---------------------------------------------------------------------------
// Fused QKV projection: grid (12, 64). bx>>2 selects Q/K/V.
// ---------------------------------------------------------------------------
__global__ __launch_bounds__(256, 2)
void gemm_qkv(const __half* __restrict__ A,
              const __half* __restrict__ Bq, const __half* __restrict__ Bk,
              const __half* __restrict__ Bv,
              const float* __restrict__ bq, const float* __restrict__ bk,
              const float* __restrict__ bv,
              __half* __restrict__ Oq, __half* __restrict__ Ok,
              __half* __restrict__ Ovt)
{
    extern __shared__ __half dsm[];

    const int tid = threadIdx.x;
    const int lane = tid & 31, wid = tid >> 5;
    const int wm = wid & 3, wn = wid >> 2;
    const int sel = blockIdx.x >> 2, bx = blockIdx.x & 3;
    const int by = blockIdx.y;
    const int N = DM, K = DM;

    const __half* B  = (sel == 0) ? Bq : (sel == 1) ? Bk : Bv;
    const float* bia_p = (sel == 0) ? bq : (sel == 1) ? bk : bv;

    const __half* Ag = A + (size_t)(by*128)*K;
    const __half* Bg = B + (size_t)bx*128;

    GEMM_MAINLOOP(Ag, Bg, K, N)

    const int r0 = (by*128) + wm*32 + (lane >> 2);
#pragma unroll
    for (int mi = 0; mi < 2; mi++) {
        const int gr = r0 + mi*16;
#pragma unroll
        for (int ni = 0; ni < 8; ni++) {
            const int gc = (bx*128) + wn*64 + (ni >> 1)*16 + (ni & 1)*8
                         + ((lane & 3) << 1);
            const float2 bia = *(const float2*)(bia_p + gc);
            float2 v0 = make_float2(acc[mi][ni][0] + bia.x, acc[mi][ni][1] + bia.y);
            float2 v1 = make_float2(acc[mi][ni][2] + bia.x, acc[mi][ni][3] + bia.y);
            if (sel == 0) {
                *(__half2*)(Oq + (size_t)gr*N + gc) =
                    __floats2half2_rn(v0.x*0.125f, v0.y*0.125f);
                *(__half2*)(Oq + (size_t)(gr+8)*N + gc) =
                    __floats2half2_rn(v1.x*0.125f, v1.y*0.125f);
            } else if (sel == 1) {
                *(__half2*)(Ok + (size_t)gr*N + gc)     = __floats2half2_rn(v0.x, v0.y);
                *(__half2*)(Ok + (size_t)(gr+8)*N + gc) = __floats2half2_rn(v1.x, v1.y);
            } else {
                Ovt[(size_t)gc*ROWS + gr]         = __float2half_rn(v0.x);
                Ovt[(size_t)(gc+1)*ROWS + gr]     = __float2half_rn(v0.y);
                Ovt[(size_t)gc*ROWS + gr + 8]     = __float2half_rn(v1.x);
                Ovt[(size_t)(gc+1)*ROWS + gr + 8] = __float2half_rn(v1.y);
            }
        }
    }
}

// ---------------------------------------------------------------------------
// FP16 flash attention, 64 q-rows / 128 threads / 4 warps per CTA,
// 2 CTAs per SM. Softmax exp via ex2.approx.f16x2 (h2exp2).
// ---------------------------------------------------------------------------
#define AT_PA 136
#define AT_PK 72
#define AT_AH (64*AT_PA)
#define AT_KH (128*AT_PK)
#define AT_VH (64*AT_PA)
#define AT_OFF_K AT_AH
#define AT_OFF_V (AT_OFF_K + 2*AT_KH)
#define AT_SMEM_BYTES ((AT_OFF_V + 2*AT_VH)*2)   // 89088 B
#define LOG2E 1.44269504f

__global__ __launch_bounds__(128, 2)
void attn_f16(const __half* __restrict__ Qh, const __half* __restrict__ Kh,
              const __half* __restrict__ Vth, __half* __restrict__ Oh)
{
    extern __shared__ __half smh[];
    __half* sA = smh;

    const int n = blockIdx.z, h = blockIdx.y;
    const int tid = threadIdx.x, lane = tid & 31, w = tid >> 5;
    const size_t base  = ((size_t)n*SEQ)*DM + h*EHEAD;
    const size_t vbase = ((size_t)h*EHEAD)*ROWS + (size_t)n*SEQ;
    const int q0 = blockIdx.x * 64;

    const uint32_t sAu = smem_u32(sA);
    const uint32_t sKu = smem_u32(smh + AT_OFF_K);
    const uint32_t sVu = smem_u32(smh + AT_OFF_V);

#pragma unroll
    for (int j = 0; j < 4; j++) {
        int idx = j*128 + tid;
        int r = idx >> 3, c8 = (idx & 7) << 3;
        cpa16(sAu + (uint32_t)((r*AT_PA + c8) << 1),
              Qh + base + (size_t)(q0 + r)*DM + c8);
    }
    cpa_commit();
#pragma unroll
    for (int j = 0; j < 8; j++) {
        int idx = j*128 + tid;
        int r = idx >> 3, c8 = (idx & 7) << 3;
        cpa16(sKu + (uint32_t)((r*AT_PK + c8) << 1),
              Kh + base + (size_t)r*DM + c8);
    }
#pragma unroll
    for (int j = 0; j < 8; j++) {
        int idx = j*128 + tid;
        int r = idx >> 4, c8 = (idx & 15) << 3;
        cpa16(sVu + (uint32_t)((r*AT_PA + c8) << 1),
              Vth + vbase + (size_t)r*ROWS + c8);
    }
    cpa_commit();

    cpa_wait<1>();
    __syncthreads();

    const uint32_t aBase = sAu + (((w*16 + (lane & 15))*AT_PA + (lane >> 4)*8) << 1);
    uint32_t aQ[4][4];
#pragma unroll
    for (int ks = 0; ks < 4; ks++) ldsm4(aQ[ks], aBase + ks*32);

    uint32_t bK[8], bV[4];
#pragma unroll
    for (int p = 0; p < 8; p++)
        bK[p] = sKu + (((p*16 + (lane & 7) + ((lane >> 3) & 1)*8)*AT_PK
                        + (lane >> 4)*8) << 1);
#pragma unroll
    for (int p = 0; p < 4; p++)
        bV[p] = sVu + (((p*16 + (lane & 7) + ((lane >> 3) & 1)*8)*AT_PA
                        + (lane >> 4)*8) << 1);

    float accO[8][4];
#pragma unroll
    for (int ni = 0; ni < 8; ni++)
#pragma unroll
        for (int c = 0; c < 4; c++) accO[ni][c] = 0.f;
    float m0 = -1e30f, m1 = -1e30f, l0 = 0.f, l1 = 0.f;

    const int rA = w*16 + (lane >> 2);
    __half* pr0 = &sA[rA*AT_PA + 2*(lane & 3)];
    __half* pr1 = pr0 + 8*AT_PA;

    for (int kt = 0; kt < SEQ/128; kt++) {
        const int buf = kt & 1;
        if (kt + 1 < SEQ/128) {
            const int nb = buf ^ 1;
            const uint32_t ko = (uint32_t)(nb * AT_KH) << 1;
            const uint32_t vo = (uint32_t)(nb * AT_VH) << 1;
#pragma unroll
            for (int j = 0; j < 8; j++) {
                int idx = j*128 + tid;
                int r = idx >> 3, c8 = (idx & 7) << 3;
                cpa16(sKu + ko + (uint32_t)((r*AT_PK + c8) << 1),
                      Kh + base + (size_t)((kt+1)*128 + r)*DM + c8);
            }
#pragma unroll
            for (int j = 0; j < 8; j++) {
                int idx = j*128 + tid;
                int r = idx >> 4, c8 = (idx & 15) << 3;
                cpa16(sVu + vo + (uint32_t)((r*AT_PA + c8) << 1),
                      Vth + vbase + (size_t)r*ROWS + (kt+1)*128 + c8);
            }
            cpa_commit();
            cpa_wait<1>();
        } else {
            cpa_wait<0>();
        }
        __syncthreads();

        const uint32_t ko = (uint32_t)(buf * AT_KH) << 1;
        const uint32_t vo = (uint32_t)(buf * AT_VH) << 1;

        // ---- S = Q K^T ----
        float accS[16][4];
#pragma unroll
        for (int t = 0; t < 16; t++)
#pragma unroll
            for (int c = 0; c < 4; c++) accS[t][c] = 0.f;
#pragma unroll
        for (int ks = 0; ks < 4; ks++) {
#pragma unroll
            for (int p = 0; p < 8; p++) {
                uint32_t bf[4];
                ldsm4(bf, bK[p] + ko + ks*32);
                mma_f16(accS[2*p],   aQ[ks], bf[0], bf[2]);
                mma_f16(accS[2*p+1], aQ[ks], bf[1], bf[3]);
            }
        }

        // ---- online softmax (fp32 stats, fp16x2 exp) ----
        float rmax0 = -1e30f, rmax1 = -1e30f;
#pragma unroll
        for (int t = 0; t < 16; t++) {
            rmax0 = fmaxf(rmax0, fmaxf(accS[t][0], accS[t][1]));
            rmax1 = fmaxf(rmax1, fmaxf(accS[t][2], accS[t][3]));
        }
        rmax0 = fmaxf(rmax0, __shfl_xor_sync(0xffffffffu, rmax0, 1));
        rmax0 = fmaxf(rmax0, __shfl_xor_sync(0xffffffffu, rmax0, 2));
        rmax1 = fmaxf(rmax1, __shfl_xor_sync(0xffffffffu, rmax1, 1));
        rmax1 = fmaxf(rmax1, __shfl_xor_sync(0xffffffffu, rmax1, 2));
        const float mn0 = fmaxf(m0, rmax0), mn1 = fmaxf(m1, rmax1);
        const float cr0 = __expf(m0 - mn0), cr1 = __expf(m1 - mn1);
        m0 = mn0; m1 = mn1;
        l0 *= cr0; l1 *= cr1;
#pragma unroll
        for (int ni = 0; ni < 8; ni++) {
            accO[ni][0] *= cr0; accO[ni][1] *= cr0;
            accO[ni][2] *= cr1; accO[ni][3] *= cr1;
        }
#pragma unroll
        for (int t = 0; t < 16; t++) {
            __half2 a0 = __floats2half2_rn((accS[t][0] - m0)*LOG2E,
                                           (accS[t][1] - m0)*LOG2E);
            __half2 a1 = __floats2half2_rn((accS[t][2] - m1)*LOG2E,
                                           (accS[t][3] - m1)*LOG2E);
            __half2 p0 = h2exp2(a0);
            __half2 p1 = h2exp2(a1);
            *(__half2*)(pr0 + t*8) = p0;
            *(__half2*)(pr1 + t*8) = p1;
            float2 f0 = __half22float2(p0);
            float2 f1 = __half22float2(p1);
            l0 += f0.x + f0.y;
            l1 += f1.x + f1.y;
        }
        __syncwarp();

        // ---- O += P V ----
#pragma unroll
        for (int ks = 0; ks < 8; ks++) {
            uint32_t aP[4];
            ldsm4(aP, aBase + ks*32);
#pragma unroll
            for (int p = 0; p < 4; p++) {
                uint32_t bf[4];
                ldsm4(bf, bV[p] + vo + ks*32);
                mma_f16(accO[2*p],   aP, bf[0], bf[2]);
                mma_f16(accO[2*p+1], aP, bf[1], bf[3]);
            }
        }
        __syncthreads();
    }

    l0 += __shfl_xor_sync(0xffffffffu, l0, 1);
    l0 += __shfl_xor_sync(0xffffffffu, l0, 2);
    l1 += __shfl_xor_sync(0xffffffffu, l1, 1);
    l1 += __shfl_xor_sync(0xffffffffu, l1, 2);
    const float inv0 = 1.f / l0, inv1 = 1.f / l1;
    const int gr0 = q0 + w*16 + (lane >> 2);
    const int cc = 2*(lane & 3);
#pragma unroll
    for (int ni = 0; ni < 8; ni++) {
        *(__half2*)(Oh + base + (size_t)gr0*DM + ni*8 + cc) =
            __floats2half2_rn(accO[ni][0]*inv0, accO[ni][1]*inv0);
        *(__half2*)(Oh + base + (size_t)(gr0+8)*DM + ni*8 + cc) =
            __floats2half2_rn(accO[ni][2]*inv1, accO[ni][3]*inv1);
    }
}

// ---------------------------------------------------------------------------
// LayerNorm (512): one WARP per row, 256 threads = 8 rows/CTA, shfl-only.
// ---------------------------------------------------------------------------
__global__ __launch_bounds__(256)
void ln_kernel(const float* __restrict__ in, const float* __restrict__ gamma,
               const float* __restrict__ beta, float* __restrict__ out,
               __half* __restrict__ out16)
{
    const int w = threadIdx.x >> 5, lane = threadIdx.x & 31;
    const int row = blockIdx.x*8 + w;
    const float4* p = (const float4*)(in + (size_t)row*DM);

    float4 v[4];
    float s = 0.f, sq = 0.f;
#pragma unroll
    for (int i = 0; i < 4; i++) {
        v[i] = p[lane + 32*i];
        s  += v[i].x + v[i].y + v[i].z + v[i].w;
        sq += v[i].x*v[i].x + v[i].y*v[i].y + v[i].z*v[i].z + v[i].w*v[i].w;
    }
#pragma unroll
    for (int o = 16; o; o >>= 1) {
        s  += __shfl_xor_sync(0xffffffffu, s,  o);
        sq += __shfl_xor_sync(0xffffffffu, sq, o);
    }
    const float mean = s * (1.f / DM);
    const float var  = sq * (1.f / DM) - mean * mean;
    const float inv  = rsqrtf(var + LN_EPS);

    float4* op = (float4*)(out + (size_t)row*DM);
    uint2*  hp = out16 ? (uint2*)(out16 + (size_t)row*DM) : nullptr;
#pragma unroll
    for (int i = 0; i < 4; i++) {
        const float4 g4 = ((const float4*)gamma)[lane + 32*i];
        const float4 b4 = ((const float4*)beta)[lane + 32*i];
        float4 o4;
        o4.x = (v[i].x - mean)*inv*g4.x + b4.x;
        o4.y = (v[i].y - mean)*inv*g4.y + b4.y;
        o4.z = (v[i].z - mean)*inv*g4.z + b4.z;
        o4.w = (v[i].w - mean)*inv*g4.w + b4.w;
        op[lane + 32*i] = o4;
        if (hp) {
            uint2 h;
            h.x = f2h2(o4.x, o4.y);
            h.y = f2h2(o4.z, o4.w);
            hp[lane + 32*i] = h;
        }
    }
}

// ---------------------------------------------------------------------------
extern "C" void kernel_launch(void* const* d_in, const int* in_sizes, int n_in,
                              void* d_out, int out_size)
{
    const float* x   = (const float*)d_in[0];
    const float* Wq  = (const float*)d_in[1];
    const float* bq  = (const float*)d_in[2];
    const float* Wk  = (const float*)d_in[3];
    const float* bk  = (const float*)d_in[4];
    const float* Wv  = (const float*)d_in[5];
    const float* bv  = (const float*)d_in[6];
    const float* Wo  = (const float*)d_in[7];
    const float* bo  = (const float*)d_in[8];
    const float* W1  = (const float*)d_in[9];
    const float* b1  = (const float*)d_in[10];
    const float* W2  = (const float*)d_in[11];
    const float* b2  = (const float*)d_in[12];
    const float* g1  = (const float*)d_in[13];
    const float* be1 = (const float*)d_in[14];
    const float* g2  = (const float*)d_in[15];
    const float* be2 = (const float*)d_in[16];

    __half *qh, *kh, *vth, *oh, *xh, *h1h, *ffh;
    __half *wqh, *wkh, *wvh, *woh, *w1h, *w2h;
    float *hb, *h1, *h2, *xb;
    cudaGetSymbolAddress((void**)&qh,  g_qh);
    cudaGetSymbolAddress((void**)&kh,  g_kh);
    cudaGetSymbolAddress((void**)&vth, g_vth);
    cudaGetSymbolAddress((void**)&oh,  g_oh);
    cudaGetSymbolAddress((void**)&xh,  g_xh);
    cudaGetSymbolAddress((void**)&h1h, g_h1h);
    cudaGetSymbolAddress((void**)&ffh, g_ffh);
    cudaGetSymbolAddress((void**)&hb,  g_h);
    cudaGetSymbolAddress((void**)&h1,  g_h1);
    cudaGetSymbolAddress((void**)&h2,  g_h2);
    cudaGetSymbolAddress((void**)&xb,  g_x);
    cudaGetSymbolAddress((void**)&wqh, g_wq);
    cudaGetSymbolAddress((void**)&wkh, g_wk);
    cudaGetSymbolAddress((void**)&wvh, g_wv);
    cudaGetSymbolAddress((void**)&woh, g_wo);
    cudaGetSymbolAddress((void**)&w1h, g_w1);
    cudaGetSymbolAddress((void**)&w2h, g_w2);

    cudaFuncSetAttribute(attn_f16, cudaFuncAttributeMaxDynamicSharedMemorySize,
                         AT_SMEM_BYTES);
    cudaFuncSetAttribute(gemm_h<1>, cudaFuncAttributeMaxDynamicSharedMemorySize,
                         GSMEM_BYTES);
    cudaFuncSetAttribute(gemm_h<2>, cudaFuncAttributeMaxDynamicSharedMemorySize,
                         GSMEM_BYTES);
    cudaFuncSetAttribute(gemm_qkv, cudaFuncAttributeMaxDynamicSharedMemorySize,
                         GSMEM_BYTES);

    // ---- one launch: fp32 -> fp16 for 6 weight arrays + layer-0 input ----
    {
        const int nqkv = NLAYERS*DM*DM/4;
        const int nff  = NLAYERS*DM*DFF/4;
        const int nx   = ROWS*DM/4;
        const int maxb = (nff + 255) / 256;
        dim3 g(maxb, 7);
        f2h_all<<<g, 256>>>((const float4*)Wq, (uint2*)wqh, nqkv,
                            (const float4*)Wk, (uint2*)wkh, nqkv,
                            (const float4*)Wv, (uint2*)wvh, nqkv,
                            (const float4*)Wo, (uint2*)woh, nqkv,
                            (const float4*)W1, (uint2*)w1h, nff,
                            (const float4*)W2, (uint2*)w2h, nff,
                            (const float4*)x,  (uint2*)xh,  nx);
    }

    const dim3 gQKV(12, ROWS / 128);           // (12, 64) fused QKV
    const dim3 gProj(DM / 128, ROWS / 128);    // (4, 64)
    const dim3 gFF1 (DFF / 128, ROWS / 128);   // (16, 64)
    const dim3 gAttn(SEQ / 64, NHEAD, NB);     // (16, 8, 8)
    const dim3 gLN(ROWS / 8);                  // 1024 blocks, warp-per-row

    const float* hin = x;
    for (int l = 0; l < NLAYERS; l++) {
        const __half* wq = wqh + (size_t)l*DM*DM;
        const __half* wk = wkh + (size_t)l*DM*DM;
        const __half* wv = wvh + (size_t)l*DM*DM;
        const __half* wo = woh + (size_t)l*DM*DM;
        const __half* w1 = w1h + (size_t)l*DM*DFF;
        const __half* w2 = w2h + (size_t)l*DFF*DM;

        gemm_qkv<<<gQKV, 256, GSMEM_BYTES>>>(xh, wq, wk, wv,
                                             bq + l*DM, bk + l*DM, bv + l*DM,
                                             qh, kh, vth);

        attn_f16<<<gAttn, 128, AT_SMEM_BYTES>>>(qh, kh, vth, oh);

        gemm_h<2><<<gProj, 256, GSMEM_BYTES>>>(oh, wo, bo + l*DM, hin, hb,
                                               ROWS, DM, DM);
        ln_kernel<<<gLN, 256>>>(hb, g1 + l*DM, be1 + l*DM, h1, h1h);

        gemm_h<1><<<gFF1, 256, GSMEM_BYTES>>>(h1h, w1, b1 + l*DFF, nullptr, ffh,
                                              ROWS, DFF, DM);
        gemm_h<2><<<gProj, 256, GSMEM_BYTES>>>(ffh, w2, b2 + l*DM, h1, h2,
                                               ROWS, DM, DFF);

        float* lnout = (l == NLAYERS - 1) ? (float*)d_out : xb;
        __half* lnout16 = (l == NLAYERS - 1) ? (__half*)nullptr : xh;
        ln_kernel<<<gLN, 256>>>(h2, g2 + l*DM, be2 + l*DM, lnout, lnout16);
        hin = xb;
    }
}

// round 15
// speedup vs baseline: 1.1182x; 1.0343x over previous
#include <cuda_runtime.h>
#include <cuda_fp16.h>
#include <cstdint>
#include <cstddef>

// Problem constants
#define DM      512
#define DFF     2048
#define NB      8
#define SEQ     1024
#define NHEAD   8
#define EHEAD   64
#define ROWS    (NB*SEQ)     // 8192
#define NLAYERS 4
#define LN_EPS  1e-5f

// ---------------- scratch (device globals; no allocations allowed) --------
__device__ __half g_qh [ROWS*DM];    // Q (pre-scaled 1/8)
__device__ __half g_kh [ROWS*DM];
__device__ __half g_vth[DM*ROWS];    // V^T [col][token]
__device__ __half g_oh [ROWS*DM];    // attention out
__device__ __half g_xh [ROWS*DM];    // fp16 copy of layer input
__device__ __half g_h1h[ROWS*DM];    // fp16 copy of post-LN1
__device__ __half g_ffh[ROWS*DFF];   // ReLU(FFN1) in fp16
__device__ float  g_h  [ROWS*DM];
__device__ float  g_h1 [ROWS*DM];
__device__ float  g_h2 [ROWS*DM];
__device__ float  g_x  [ROWS*DM];
// fp16 weights (converted once per launch)
__device__ __half g_wq[NLAYERS*DM*DM];
__device__ __half g_wk[NLAYERS*DM*DM];
__device__ __half g_wv[NLAYERS*DM*DM];
__device__ __half g_wo[NLAYERS*DM*DM];
__device__ __half g_w1[NLAYERS*DM*DFF];
__device__ __half g_w2[NLAYERS*DFF*DM];

// ---------------- helpers ---------------------------------------------------
__device__ __forceinline__ uint32_t f2h2(float a, float b) {
    __half2 h = __floats2half2_rn(a, b);
    return *(uint32_t*)&h;
}
__device__ __forceinline__ void ldsm4(uint32_t* r, uint32_t addr) {
    asm volatile("ldmatrix.sync.aligned.m8n8.x4.shared.b16 {%0,%1,%2,%3}, [%4];\n"
                 : "=r"(r[0]), "=r"(r[1]), "=r"(r[2]), "=r"(r[3]) : "r"(addr));
}
__device__ __forceinline__ void ldsm4t(uint32_t* r, uint32_t addr) {
    asm volatile("ldmatrix.sync.aligned.m8n8.x4.trans.shared.b16 {%0,%1,%2,%3}, [%4];\n"
                 : "=r"(r[0]), "=r"(r[1]), "=r"(r[2]), "=r"(r[3]) : "r"(addr));
}
__device__ __forceinline__ void mma_f16(float* d, const uint32_t* a,
                                        uint32_t b0, uint32_t b1) {
    asm volatile(
        "mma.sync.aligned.m16n8k16.row.col.f32.f16.f16.f32 "
        "{%0,%1,%2,%3},{%4,%5,%6,%7},{%8,%9},{%0,%1,%2,%3};\n"
        : "+f"(d[0]), "+f"(d[1]), "+f"(d[2]), "+f"(d[3])
        : "r"(a[0]), "r"(a[1]), "r"(a[2]), "r"(a[3]), "r"(b0), "r"(b1));
}
__device__ __forceinline__ uint32_t smem_u32(const void* p) {
    return (uint32_t)__cvta_generic_to_shared(p);
}
// cp.async with L1 bypass (cg): fills have zero reuse, keep them out of L1tex
__device__ __forceinline__ void cpa16(uint32_t dst, const void* src) {
    asm volatile("cp.async.cg.shared.global [%0], [%1], 16;\n"
                 :: "r"(dst), "l"(src) : "memory");
}
__device__ __forceinline__ void cpa_commit() {
    asm volatile("cp.async.commit_group;\n" ::: "memory");
}
template<int N>
__device__ __forceinline__ void cpa_wait() {
    asm volatile("cp.async.wait_group %0;\n" :: "n"(N) : "memory");
}

// ---------------- fp32 -> fp16 bulk convert (all 7 arrays, one launch) -----
__global__ __launch_bounds__(256)
void f2h_all(const float4* s0, uint2* d0, int n0,
             const float4* s1, uint2* d1, int n1,
             const float4* s2, uint2* d2, int n2,
             const float4* s3, uint2* d3, int n3,
             const float4* s4, uint2* d4, int n4,
             const float4* s5, uint2* d5, int n5,
             const float4* s6, uint2* d6, int n6)
{
    const float4* s; uint2* d; int n;
    switch (blockIdx.y) {
        case 0: s = s0; d = d0; n = n0; break;
        case 1: s = s1; d = d1; n = n1; break;
        case 2: s = s2; d = d2; n = n2; break;
        case 3: s = s3; d = d3; n = n3; break;
        case 4: s = s4; d = d4; n = n4; break;
        case 5: s = s5; d = d5; n = n5; break;
        default: s = s6; d = d6; n = n6; break;
    }
    int i = blockIdx.x*blockDim.x + threadIdx.x;
    if (i < n) {
        float4 v = s[i];
        uint2 o;
        o.x = f2h2(v.x, v.y);
        o.y = f2h2(v.z, v.w);
        d[i] = o;
    }
}

// ---------------------------------------------------------------------------
// GEMM core: BM=BN=128, BK=64, 256 thr (8 warps, 4m x 2n, warp tile 32x64),
// m16n8k16, 3-stage cp.async ring in dynamic smem, ONE sync per 64-wide
// k-tile (half the barrier count of the BK=32 version).
// ---------------------------------------------------------------------------
#define GPA 72                     // A pitch in halfs (64 + 8 pad)
#define GPB 136                    // B pitch in halfs (128 + 8 pad)
#define ABUF (128*GPA)             // halfs per A stage (9216)
#define BBUF (64*GPB)              // halfs per B stage (8704)
#define GSTAGES 3
#define GSMEM_BYTES (GSTAGES*(ABUF+BBUF)*2)   // 107520 B

// issue one 64-wide k-tile into stage st: 4 A chunks + 4 B chunks per thread
#define GEMM_ISSUE(Aptr, Bptr, Kdim, Ndim, st, k0)                              \
    {                                                                           \
        const uint32_t oA = (uint32_t)((st)*ABUF*2);                            \
        const uint32_t oB = (uint32_t)((st)*BBUF*2);                            \
        _Pragma("unroll")                                                       \
        for (int j = 0; j < 4; j++)                                             \
            cpa16(sAu + oA + dA0 + (uint32_t)(j*32*GPA*2),                      \
                  (Aptr) + (size_t)(ar0 + 32*j)*(Kdim) + (k0) + ac0);           \
        _Pragma("unroll")                                                       \
        for (int j = 0; j < 4; j++)                                             \
            cpa16(sBu + oB + dB0 + (uint32_t)(j*16*GPB*2),                      \
                  (Bptr) + (size_t)((k0) + bk0 + 16*j)*(Ndim) + bn0);           \
    }

#define GEMM_MAINLOOP(Aptr, Bptr, Kdim, Ndim)                                   \
    __half* smA = dsm;                                                          \
    __half* smB = dsm + GSTAGES*ABUF;                                           \
    const int ar0 = tid >> 3,  ac0 = (tid & 7) << 3;                            \
    const int bk0 = tid >> 4,  bn0 = (tid & 15) << 3;                           \
    const uint32_t sAu = smem_u32(smA);                                         \
    const uint32_t sBu = smem_u32(smB);                                         \
    const uint32_t dA0 = (uint32_t)((ar0*GPA + ac0) << 1);                      \
    const uint32_t dB0 = (uint32_t)((bk0*GPB + bn0) << 1);                      \
    uint32_t aAd[2], bAd[4];                                                    \
    _Pragma("unroll")                                                           \
    for (int mi = 0; mi < 2; mi++)                                              \
        aAd[mi] = sAu + (((wm*32 + mi*16 + (lane & 15))*GPA + (lane >> 4)*8) << 1); \
    _Pragma("unroll")                                                           \
    for (int nt = 0; nt < 4; nt++)                                              \
        bAd[nt] = sBu + ((((lane & 7) + ((lane >> 3) & 1)*8)*GPB                \
                          + wn*64 + nt*16 + (lane >> 4)*8) << 1);               \
    float acc[2][8][4];                                                         \
    _Pragma("unroll")                                                           \
    for (int mi = 0; mi < 2; mi++)                                              \
        _Pragma("unroll")                                                       \
        for (int ni = 0; ni < 8; ni++)                                          \
            _Pragma("unroll")                                                   \
            for (int c = 0; c < 4; c++) acc[mi][ni][c] = 0.f;                   \
    const int KT = (Kdim) >> 6;                                                 \
    GEMM_ISSUE(Aptr, Bptr, Kdim, Ndim, 0, 0)  cpa_commit();                     \
    GEMM_ISSUE(Aptr, Bptr, Kdim, Ndim, 1, 64) cpa_commit();                     \
    int st = 0, rs = 2;                                                         \
    for (int kt = 0; kt < KT; kt++) {                                           \
        cpa_wait<1>();                                                          \
        __syncthreads();                                                        \
        if (kt + 2 < KT) {                                                      \
            GEMM_ISSUE(Aptr, Bptr, Kdim, Ndim, rs, (kt + 2)*64)                 \
        }                                                                       \
        cpa_commit();                                                           \
        const uint32_t boA = (uint32_t)(st*ABUF*2);                             \
        const uint32_t boB = (uint32_t)(st*BBUF*2);                             \
        _Pragma("unroll")                                                       \
        for (int kh = 0; kh < 4; kh++) {                                        \
            uint32_t af[2][4], bf[4][4];                                        \
            ldsm4(af[0], aAd[0] + boA + kh*32);                                 \
            ldsm4(af[1], aAd[1] + boA + kh*32);                                 \
            _Pragma("unroll")                                                   \
            for (int nt = 0; nt < 4; nt++)                                      \
                ldsm4t(bf[nt], bAd[nt] + boB + kh*16*GPB*2);                    \
            _Pragma("unroll")                                                   \
            for (int nt = 0; nt < 4; nt++) {                                    \
                _Pragma("unroll")                                               \
                for (int mi = 0; mi < 2; mi++) {                                \
                    mma_f16(acc[mi][2*nt],   af[mi], bf[nt][0], bf[nt][1]);     \
                    mma_f16(acc[mi][2*nt+1], af[mi], bf[nt][2], bf[nt][3]);     \
                }                                                               \
            }                                                                   \
        }                                                                       \
        st = (st + 1 == GSTAGES) ? 0 : st + 1;                                  \
        rs = (rs + 1 == GSTAGES) ? 0 : rs + 1;                                  \
    }

// ---------------------------------------------------------------------------
// General fp16 GEMM with fused epilogues.
//  EPI 1: half out, bias+relu   EPI 2: f32 out, bias+residual
// ---------------------------------------------------------------------------
template<int EPI>
__global__ __launch_bounds__(256, 2)
void gemm_h(const __half* __restrict__ A, const __half* __restrict__ B,
            const float* __restrict__ bias, const float* __restrict__ res,
            void* __restrict__ Cv, int M, int N, int K)
{
    extern __shared__ __half dsm[];

    const int tid = threadIdx.x;
    const int lane = tid & 31, wid = tid >> 5;
    const int wm = wid & 3, wn = wid >> 2;
    const int bx = blockIdx.x, by = blockIdx.y;

    const __half* Ag = A + (size_t)(by*128)*K;
    const __half* Bg = B + (size_t)bx*128;

    GEMM_MAINLOOP(Ag, Bg, K, N)

    const int r0 = (by*128) + wm*32 + (lane >> 2);
#pragma unroll
    for (int mi = 0; mi < 2; mi++) {
        const int gr = r0 + mi*16;
#pragma unroll
        for (int ni = 0; ni < 8; ni++) {
            const int gc = (bx*128) + wn*64 + (ni >> 1)*16 + (ni & 1)*8
                         + ((lane & 3) << 1);
            const float2 bia = *(const float2*)(bias + gc);
            float2 v0 = make_float2(acc[mi][ni][0] + bia.x, acc[mi][ni][1] + bia.y);
            float2 v1 = make_float2(acc[mi][ni][2] + bia.x, acc[mi][ni][3] + bia.y);
            if (EPI == 1) {
                v0.x = fmaxf(v0.x, 0.f); v0.y = fmaxf(v0.y, 0.f);
                v1.x = fmaxf(v1.x, 0.f); v1.y = fmaxf(v1.y, 0.f);
                __half* Ch = (__half*)Cv;
                *(__half2*)(Ch + (size_t)gr*N + gc)     = __floats2half2_rn(v0.x, v0.y);
                *(__half2*)(Ch + (size_t)(gr+8)*N + gc) = __floats2half2_rn(v1.x, v1.y);
            } else {  // EPI == 2
                const float2 r_0 = *(const float2*)(res + (size_t)gr*N + gc);
                const float2 r_1 = *(const float2*)(res + (size_t)(gr+8)*N + gc);
                v0.x += r_0.x; v0.y += r_0.y;
                v1.x += r_1.x; v1.y += r_1.y;
                float* Cf = (float*)Cv;
                *(float2*)(Cf + (size_t)gr*N + gc)     = v0;
                *(float2*)(Cf + (size_t)(gr+8)*N + gc) = v1;
            }
        }
    }
}

// ---------------------------------------------------------------------------
// Fused QKV projection: grid (12, 64). bx>>2 selects Q/K/V.
// ---------------------------------------------------------------------------
__global__ __launch_bounds__(256, 2)
void gemm_qkv(const __half* __restrict__ A,
              const __half* __restrict__ Bq, const __half* __restrict__ Bk,
              const __half* __restrict__ Bv,
              const float* __restrict__ bq, const float* __restrict__ bk,
              const float* __restrict__ bv,
              __half* __restrict__ Oq, __half* __restrict__ Ok,
              __half* __restrict__ Ovt)
{
    extern __shared__ __half dsm[];

    const int tid = threadIdx.x;
    const int lane = tid & 31, wid = tid >> 5;
    const int wm = wid & 3, wn = wid >> 2;
    const int sel = blockIdx.x >> 2, bx = blockIdx.x & 3;
    const int by = blockIdx.y;
    const int N = DM, K = DM;

    const __half* B  = (sel == 0) ? Bq : (sel == 1) ? Bk : Bv;
    const float* bia_p = (sel == 0) ? bq : (sel == 1) ? bk : bv;

    const __half* Ag = A + (size_t)(by*128)*K;
    const __half* Bg = B + (size_t)bx*128;

    GEMM_MAINLOOP(Ag, Bg, K, N)

    const int r0 = (by*128) + wm*32 + (lane >> 2);
#pragma unroll
    for (int mi = 0; mi < 2; mi++) {
        const int gr = r0 + mi*16;
#pragma unroll
        for (int ni = 0; ni < 8; ni++) {
            const int gc = (bx*128) + wn*64 + (ni >> 1)*16 + (ni & 1)*8
                         + ((lane & 3) << 1);
            const float2 bia = *(const float2*)(bia_p + gc);
            float2 v0 = make_float2(acc[mi][ni][0] + bia.x, acc[mi][ni][1] + bia.y);
            float2 v1 = make_float2(acc[mi][ni][2] + bia.x, acc[mi][ni][3] + bia.y);
            if (sel == 0) {
                *(__half2*)(Oq + (size_t)gr*N + gc) =
                    __floats2half2_rn(v0.x*0.125f, v0.y*0.125f);
                *(__half2*)(Oq + (size_t)(gr+8)*N + gc) =
                    __floats2half2_rn(v1.x*0.125f, v1.y*0.125f);
            } else if (sel == 1) {
                *(__half2*)(Ok + (size_t)gr*N + gc)     = __floats2half2_rn(v0.x, v0.y);
                *(__half2*)(Ok + (size_t)(gr+8)*N + gc) = __floats2half2_rn(v1.x, v1.y);
            } else {
                Ovt[(size_t)gc*ROWS + gr]         = __float2half_rn(v0.x);
                Ovt[(size_t)(gc+1)*ROWS + gr]     = __float2half_rn(v0.y);
                Ovt[(size_t)gc*ROWS + gr + 8]     = __float2half_rn(v1.x);
                Ovt[(size_t)(gc+1)*ROWS + gr + 8] = __float2half_rn(v1.y);
            }
        }
    }
}

// ---------------------------------------------------------------------------
// FP16 flash attention, 64 q-rows / 128 threads / 4 warps per CTA,
// 2 CTAs per SM. Softmax exp via ex2.approx.f16x2 (h2exp2). (R13/R14 version)
// ---------------------------------------------------------------------------
#define AT_PA 136
#define AT_PK 72
#define AT_AH (64*AT_PA)
#define AT_KH (128*AT_PK)
#define AT_VH (64*AT_PA)
#define AT_OFF_K AT_AH
#define AT_OFF_V (AT_OFF_K + 2*AT_KH)
#define AT_SMEM_BYTES ((AT_OFF_V + 2*AT_VH)*2)   // 89088 B
#define LOG2E 1.44269504f

__global__ __launch_bounds__(128, 2)
void attn_f16(const __half* __restrict__ Qh, const __half* __restrict__ Kh,
              const __half* __restrict__ Vth, __half* __restrict__ Oh)
{
    extern __shared__ __half smh[];
    __half* sA = smh;

    const int n = blockIdx.z, h = blockIdx.y;
    const int tid = threadIdx.x, lane = tid & 31, w = tid >> 5;
    const size_t base  = ((size_t)n*SEQ)*DM + h*EHEAD;
    const size_t vbase = ((size_t)h*EHEAD)*ROWS + (size_t)n*SEQ;
    const int q0 = blockIdx.x * 64;

    const uint32_t sAu = smem_u32(sA);
    const uint32_t sKu = smem_u32(smh + AT_OFF_K);
    const uint32_t sVu = smem_u32(smh + AT_OFF_V);

#pragma unroll
    for (int j = 0; j < 4; j++) {
        int idx = j*128 + tid;
        int r = idx >> 3, c8 = (idx & 7) << 3;
        cpa16(sAu + (uint32_t)((r*AT_PA + c8) << 1),
              Qh + base + (size_t)(q0 + r)*DM + c8);
    }
    cpa_commit();
#pragma unroll
    for (int j = 0; j < 8; j++) {
        int idx = j*128 + tid;
        int r = idx >> 3, c8 = (idx & 7) << 3;
        cpa16(sKu + (uint32_t)((r*AT_PK + c8) << 1),
              Kh + base + (size_t)r*DM + c8);
    }
#pragma unroll
    for (int j = 0; j < 8; j++) {
        int idx = j*128 + tid;
        int r = idx >> 4, c8 = (idx & 15) << 3;
        cpa16(sVu + (uint32_t)((r*AT_PA + c8) << 1),
              Vth + vbase + (size_t)r*ROWS + c8);
    }
    cpa_commit();

    cpa_wait<1>();
    __syncthreads();

    const uint32_t aBase = sAu + (((w*16 + (lane & 15))*AT_PA + (lane >> 4)*8) << 1);
    uint32_t aQ[4][4];
#pragma unroll
    for (int ks = 0; ks < 4; ks++) ldsm4(aQ[ks], aBase + ks*32);

    uint32_t bK[8], bV[4];
#pragma unroll
    for (int p = 0; p < 8; p++)
        bK[p] = sKu + (((p*16 + (lane & 7) + ((lane >> 3) & 1)*8)*AT_PK
                        + (lane >> 4)*8) << 1);
#pragma unroll
    for (int p = 0; p < 4; p++)
        bV[p] = sVu + (((p*16 + (lane & 7) + ((lane >> 3) & 1)*8)*AT_PA
                        + (lane >> 4)*8) << 1);

    float accO[8][4];
#pragma unroll
    for (int ni = 0; ni < 8; ni++)
#pragma unroll
        for (int c = 0; c < 4; c++) accO[ni][c] = 0.f;
    float m0 = -1e30f, m1 = -1e30f, l0 = 0.f, l1 = 0.f;

    const int rA = w*16 + (lane >> 2);
    __half* pr0 = &sA[rA*AT_PA + 2*(lane & 3)];
    __half* pr1 = pr0 + 8*AT_PA;

    for (int kt = 0; kt < SEQ/128; kt++) {
        const int buf = kt & 1;
        if (kt + 1 < SEQ/128) {
            const int nb = buf ^ 1;
            const uint32_t ko = (uint32_t)(nb * AT_KH) << 1;
            const uint32_t vo = (uint32_t)(nb * AT_VH) << 1;
#pragma unroll
            for (int j = 0; j < 8; j++) {
                int idx = j*128 + tid;
                int r = idx >> 3, c8 = (idx & 7) << 3;
                cpa16(sKu + ko + (uint32_t)((r*AT_PK + c8) << 1),
                      Kh + base + (size_t)((kt+1)*128 + r)*DM + c8);
            }
#pragma unroll
            for (int j = 0; j < 8; j++) {
                int idx = j*128 + tid;
                int r = idx >> 4, c8 = (idx & 15) << 3;
                cpa16(sVu + vo + (uint32_t)((r*AT_PA + c8) << 1),
                      Vth + vbase + (size_t)r*ROWS + (kt+1)*128 + c8);
            }
            cpa_commit();
            cpa_wait<1>();
        } else {
            cpa_wait<0>();
        }
        __syncthreads();

        const uint32_t ko = (uint32_t)(buf * AT_KH) << 1;
        const uint32_t vo = (uint32_t)(buf * AT_VH) << 1;

        // ---- S = Q K^T ----
        float accS[16][4];
#pragma unroll
        for (int t = 0; t < 16; t++)
#pragma unroll
            for (int c = 0; c < 4; c++) accS[t][c] = 0.f;
#pragma unroll
        for (int ks = 0; ks < 4; ks++) {
#pragma unroll
            for (int p = 0; p < 8; p++) {
                uint32_t bf[4];
                ldsm4(bf, bK[p] + ko + ks*32);
                mma_f16(accS[2*p],   aQ[ks], bf[0], bf[2]);
                mma_f16(accS[2*p+1], aQ[ks], bf[1], bf[3]);
            }
        }

        // ---- online softmax (fp32 stats, fp16x2 exp) ----
        float rmax0 = -1e30f, rmax1 = -1e30f;
#pragma unroll
        for (int t = 0; t < 16; t++) {
            rmax0 = fmaxf(rmax0, fmaxf(accS[t][0], accS[t][1]));
            rmax1 = fmaxf(rmax1, fmaxf(accS[t][2], accS[t][3]));
        }
        rmax0 = fmaxf(rmax0, __shfl_xor_sync(0xffffffffu, rmax0, 1));
        rmax0 = fmaxf(rmax0, __shfl_xor_sync(0xffffffffu, rmax0, 2));
        rmax1 = fmaxf(rmax1, __shfl_xor_sync(0xffffffffu, rmax1, 1));
        rmax1 = fmaxf(rmax1, __shfl_xor_sync(0xffffffffu, rmax1, 2));
        const float mn0 = fmaxf(m0, rmax0), mn1 = fmaxf(m1, rmax1);
        const float cr0 = __expf(m0 - mn0), cr1 = __expf(m1 - mn1);
        m0 = mn0; m1 = mn1;
        l0 *= cr0; l1 *= cr1;
#pragma unroll
        for (int ni = 0; ni < 8; ni++) {
            accO[ni][0] *= cr0; accO[ni][1] *= cr0;
            accO[ni][2] *= cr1; accO[ni][3] *= cr1;
        }
#pragma unroll
        for (int t = 0; t < 16; t++) {
            __half2 a0 = __floats2half2_rn((accS[t][0] - m0)*LOG2E,
                                           (accS[t][1] - m0)*LOG2E);
            __half2 a1 = __floats2half2_rn((accS[t][2] - m1)*LOG2E,
                                           (accS[t][3] - m1)*LOG2E);
            __half2 p0 = h2exp2(a0);
            __half2 p1 = h2exp2(a1);
            *(__half2*)(pr0 + t*8) = p0;
            *(__half2*)(pr1 + t*8) = p1;
            float2 f0 = __half22float2(p0);
            float2 f1 = __half22float2(p1);
            l0 += f0.x + f0.y;
            l1 += f1.x + f1.y;
        }
        __syncwarp();

        // ---- O += P V ----
#pragma unroll
        for (int ks = 0; ks < 8; ks++) {
            uint32_t aP[4];
            ldsm4(aP, aBase + ks*32);
#pragma unroll
            for (int p = 0; p < 4; p++) {
                uint32_t bf[4];
                ldsm4(bf, bV[p] + vo + ks*32);
                mma_f16(accO[2*p],   aP, bf[0], bf[2]);
                mma_f16(accO[2*p+1], aP, bf[1], bf[3]);
            }
        }
        __syncthreads();
    }

    l0 += __shfl_xor_sync(0xffffffffu, l0, 1);
    l0 += __shfl_xor_sync(0xffffffffu, l0, 2);
    l1 += __shfl_xor_sync(0xffffffffu, l1, 1);
    l1 += __shfl_xor_sync(0xffffffffu, l1, 2);
    const float inv0 = 1.f / l0, inv1 = 1.f / l1;
    const int gr0 = q0 + w*16 + (lane >> 2);
    const int cc = 2*(lane & 3);
#pragma unroll
    for (int ni = 0; ni < 8; ni++) {
        *(__half2*)(Oh + base + (size_t)gr0*DM + ni*8 + cc) =
            __floats2half2_rn(accO[ni][0]*inv0, accO[ni][1]*inv0);
        *(__half2*)(Oh + base + (size_t)(gr0+8)*DM + ni*8 + cc) =
            __floats2half2_rn(accO[ni][2]*inv1, accO[ni][3]*inv1);
    }
}

// ---------------------------------------------------------------------------
// LayerNorm (512): one WARP per row, 256 threads = 8 rows/CTA, shfl-only.
// ---------------------------------------------------------------------------
__global__ __launch_bounds__(256)
void ln_kernel(const float* __restrict__ in, const float* __restrict__ gamma,
               const float* __restrict__ beta, float* __restrict__ out,
               __half* __restrict__ out16)
{
    const int w = threadIdx.x >> 5, lane = threadIdx.x & 31;
    const int row = blockIdx.x*8 + w;
    const float4* p = (const float4*)(in + (size_t)row*DM);

    float4 v[4];
    float s = 0.f, sq = 0.f;
#pragma unroll
    for (int i = 0; i < 4; i++) {
        v[i] = p[lane + 32*i];
        s  += v[i].x + v[i].y + v[i].z + v[i].w;
        sq += v[i].x*v[i].x + v[i].y*v[i].y + v[i].z*v[i].z + v[i].w*v[i].w;
    }
#pragma unroll
    for (int o = 16; o; o >>= 1) {
        s  += __shfl_xor_sync(0xffffffffu, s,  o);
        sq += __shfl_xor_sync(0xffffffffu, sq, o);
    }
    const float mean = s * (1.f / DM);
    const float var  = sq * (1.f / DM) - mean * mean;
    const float inv  = rsqrtf(var + LN_EPS);

    float4* op = (float4*)(out + (size_t)row*DM);
    uint2*  hp = out16 ? (uint2*)(out16 + (size_t)row*DM) : nullptr;
#pragma unroll
    for (int i = 0; i < 4; i++) {
        const float4 g4 = ((const float4*)gamma)[lane + 32*i];
        const float4 b4 = ((const float4*)beta)[lane + 32*i];
        float4 o4;
        o4.x = (v[i].x - mean)*inv*g4.x + b4.x;
        o4.y = (v[i].y - mean)*inv*g4.y + b4.y;
        o4.z = (v[i].z - mean)*inv*g4.z + b4.z;
        o4.w = (v[i].w - mean)*inv*g4.w + b4.w;
        op[lane + 32*i] = o4;
        if (hp) {
            uint2 h;
            h.x = f2h2(o4.x, o4.y);
            h.y = f2h2(o4.z, o4.w);
            hp[lane + 32*i] = h;
        }
    }
}

// ---------------------------------------------------------------------------
extern "C" void kernel_launch(void* const* d_in, const int* in_sizes, int n_in,
                              void* d_out, int out_size)
{
    const float* x   = (const float*)d_in[0];
    const float* Wq  = (const float*)d_in[1];
    const float* bq  = (const float*)d_in[2];
    const float* Wk  = (const float*)d_in[3];
    const float* bk  = (const float*)d_in[4];
    const float* Wv  = (const float*)d_in[5];
    const float* bv  = (const float*)d_in[6];
    const float* Wo  = (const float*)d_in[7];
    const float* bo  = (const float*)d_in[8];
    const float* W1  = (const float*)d_in[9];
    const float* b1  = (const float*)d_in[10];
    const float* W2  = (const float*)d_in[11];
    const float* b2  = (const float*)d_in[12];
    const float* g1  = (const float*)d_in[13];
    const float* be1 = (const float*)d_in[14];
    const float* g2  = (const float*)d_in[15];
    const float* be2 = (const float*)d_in[16];

    __half *qh, *kh, *vth, *oh, *xh, *h1h, *ffh;
    __half *wqh, *wkh, *wvh, *woh, *w1h, *w2h;
    float *hb, *h1, *h2, *xb;
    cudaGetSymbolAddress((void**)&qh,  g_qh);
    cudaGetSymbolAddress((void**)&kh,  g_kh);
    cudaGetSymbolAddress((void**)&vth, g_vth);
    cudaGetSymbolAddress((void**)&oh,  g_oh);
    cudaGetSymbolAddress((void**)&xh,  g_xh);
    cudaGetSymbolAddress((void**)&h1h, g_h1h);
    cudaGetSymbolAddress((void**)&ffh, g_ffh);
    cudaGetSymbolAddress((void**)&hb,  g_h);
    cudaGetSymbolAddress((void**)&h1,  g_h1);
    cudaGetSymbolAddress((void**)&h2,  g_h2);
    cudaGetSymbolAddress((void**)&xb,  g_x);
    cudaGetSymbolAddress((void**)&wqh, g_wq);
    cudaGetSymbolAddress((void**)&wkh, g_wk);
    cudaGetSymbolAddress((void**)&wvh, g_wv);
    cudaGetSymbolAddress((void**)&woh, g_wo);
    cudaGetSymbolAddress((void**)&w1h, g_w1);
    cudaGetSymbolAddress((void**)&w2h, g_w2);

    cudaFuncSetAttribute(attn_f16, cudaFuncAttributeMaxDynamicSharedMemorySize,
                         AT_SMEM_BYTES);
    cudaFuncSetAttribute(gemm_h<1>, cudaFuncAttributeMaxDynamicSharedMemorySize,
                         GSMEM_BYTES);
    cudaFuncSetAttribute(gemm_h<2>, cudaFuncAttributeMaxDynamicSharedMemorySize,
                         GSMEM_BYTES);
    cudaFuncSetAttribute(gemm_qkv, cudaFuncAttributeMaxDynamicSharedMemorySize,
                         GSMEM_BYTES);

    // ---- one launch: fp32 -> fp16 for 6 weight arrays + layer-0 input ----
    {
        const int nqkv = NLAYERS*DM*DM/4;
        const int nff  = NLAYERS*DM*DFF/4;
        const int nx   = ROWS*DM/4;
        const int maxb = (nff + 255) / 256;
        dim3 g(maxb, 7);
        f2h_all<<<g, 256>>>((const float4*)Wq, (uint2*)wqh, nqkv,
                            (const float4*)Wk, (uint2*)wkh, nqkv,
                            (const float4*)Wv, (uint2*)wvh, nqkv,
                            (const float4*)Wo, (uint2*)woh, nqkv,
                            (const float4*)W1, (uint2*)w1h, nff,
                            (const float4*)W2, (uint2*)w2h, nff,
                            (const float4*)x,  (uint2*)xh,  nx);
    }

    const dim3 gQKV(12, ROWS / 128);           // (12, 64) fused QKV
    const dim3 gProj(DM / 128, ROWS / 128);    // (4, 64)
    const dim3 gFF1 (DFF / 128, ROWS / 128);   // (16, 64)
    const dim3 gAttn(SEQ / 64, NHEAD, NB);     // (16, 8, 8)
    const dim3 gLN(ROWS / 8);                  // 1024 blocks, warp-per-row

    const float* hin = x;
    for (int l = 0; l < NLAYERS; l++) {
        const __half* wq = wqh + (size_t)l*DM*DM;
        const __half* wk = wkh + (size_t)l*DM*DM;
        const __half* wv = wvh + (size_t)l*DM*DM;
        const __half* wo = woh + (size_t)l*DM*DM;
        const __half* w1 = w1h + (size_t)l*DM*DFF;
        const __half* w2 = w2h + (size_t)l*DFF*DM;

        gemm_qkv<<<gQKV, 256, GSMEM_BYTES>>>(xh, wq, wk, wv,
                                             bq + l*DM, bk + l*DM, bv + l*DM,
                                             qh, kh, vth);

        attn_f16<<<gAttn, 128, AT_SMEM_BYTES>>>(qh, kh, vth, oh);

        gemm_h<2><<<gProj, 256, GSMEM_BYTES>>>(oh, wo, bo + l*DM, hin, hb,
                                               ROWS, DM, DM);
        ln_kernel<<<gLN, 256>>>(hb, g1 + l*DM, be1 + l*DM, h1, h1h);

        gemm_h<1><<<gFF1, 256, GSMEM_BYTES>>>(h1h, w1, b1 + l*DFF, nullptr, ffh,
                                              ROWS, DFF, DM);
        gemm_h<2><<<gProj, 256, GSMEM_BYTES>>>(ffh, w2, b2 + l*DM, h1, h2,
                                               ROWS, DM, DFF);

        float* lnout = (l == NLAYERS - 1) ? (float*)d_out : xb;
        __half* lnout16 = (l == NLAYERS - 1) ? (__half*)nullptr : xh;
        ln_kernel<<<gLN, 256>>>(h2, g2 + l*DM, be2 + l*DM, lnout, lnout16);
        hin = xb;
    }
}